// round 10
// baseline (speedup 1.0000x reference)
#include <cuda_runtime.h>
#include <cuda_bf16.h>
#include <cstdint>

#define BB 8
#define CC 64
#define NN 4096
#define KK 16
#define EE 64
#define NPOINTS (BB*NN)            // 32768
#define CNT1 524288.0f             // B*N*K
#define CNT3 32768.0f              // B*N
#define EPSV 1e-5f

// ---- scratch (device globals: allocation-free rule) ----
__device__ float g_y1t[NPOINTS*EE];       // 8 MB  raw y1 transposed [point][c]
__device__ float g_u[NPOINTS*EE];         // 8 MB  permuted u = a1*y
__device__ float g_un[NPOINTS*EE];        // 8 MB  permuted un' = u - c1
__device__ float g_zmax[NPOINTS*EE];      // 8 MB
__device__ float g_zmin[NPOINTS*EE];      // 8 MB
__device__ float g_sum1[EE], g_sumsq1[EE];
__device__ float g_sum2[EE], g_sumsq2[EE];
__device__ float g_sum3[EE], g_sumsq3[EE];

// pack two fp32 into bf16x2 (first arg -> low half)
__device__ __forceinline__ uint32_t pack_bf2(float lo_e, float hi_e) {
    uint32_t r;
    asm("cvt.rn.bf16x2.f32 %0, %1, %2;" : "=r"(r) : "f"(hi_e), "f"(lo_e));
    return r;
}

__device__ __forceinline__ void mma16816(float d[4], const uint32_t a[4], uint32_t b0, uint32_t b1) {
    asm volatile(
        "mma.sync.aligned.m16n8k16.row.col.f32.bf16.bf16.f32 "
        "{%0,%1,%2,%3}, {%4,%5,%6,%7}, {%8,%9}, {%0,%1,%2,%3};"
        : "+f"(d[0]), "+f"(d[1]), "+f"(d[2]), "+f"(d[3])
        : "r"(a[0]), "r"(a[1]), "r"(a[2]), "r"(a[3]), "r"(b0), "r"(b1));
}

// split a packed pair (x,y) into hi (bf16) and lo (residual bf16)
__device__ __forceinline__ void split2(float x, float y, uint32_t& hi, uint32_t& lo) {
    hi = pack_bf2(x, y);
    float e0 = __uint_as_float(hi << 16);
    float e1 = __uint_as_float(hi & 0xffff0000u);
    lo = pack_bf2(x - e0, y - e1);
}

__device__ __forceinline__ uint32_t smem_u32(const void* p) {
    uint32_t a;
    asm("{ .reg .u64 t; cvta.to.shared.u64 t, %1; cvt.u32.u64 %0, t; }" : "=r"(a) : "l"(p));
    return a;
}
__device__ __forceinline__ float4 lds128(uint32_t a) {
    float4 v;
    asm volatile("ld.shared.v4.f32 {%0,%1,%2,%3}, [%4];"
                 : "=f"(v.x), "=f"(v.y), "=f"(v.z), "=f"(v.w) : "r"(a));
    return v;
}
#define CP16(d, s) asm volatile("cp.async.cg.shared.global [%0], [%1], 16;" :: "r"(d), "l"(s) : "memory")
#define CP_COMMIT() asm volatile("cp.async.commit_group;" ::: "memory")
#define CP_WAIT0()  asm volatile("cp.async.wait_group 0;" ::: "memory")

// ============================================================================
// y1t[b][n][e] = sum_c W1[e][c] * x[b][c][n];  block(0,0) zeroes accumulators
__global__ void k_y1(const float* __restrict__ x, const float* __restrict__ W1) {
    __shared__ float xs[CC][64];
    __shared__ float W1sT[CC][EE];
    int b = blockIdx.y;
    int n0 = blockIdx.x * 64;
    int t = threadIdx.x;
    if (blockIdx.x == 0 && blockIdx.y == 0 && t < EE) {
        g_sum1[t]=0.f; g_sumsq1[t]=0.f;
        g_sum2[t]=0.f; g_sumsq2[t]=0.f;
        g_sum3[t]=0.f; g_sumsq3[t]=0.f;
    }
    for (int i = t; i < CC*EE; i += 256) {
        int o = i >> 6, c = i & 63;
        W1sT[c][o] = W1[i];
    }
    for (int i = t; i < CC*64; i += 256) {
        int c = i >> 6, j = i & 63;
        xs[c][j] = x[(b*CC + c)*NN + n0 + j];
    }
    __syncthreads();
    int e = t & 63;
    int nb = (t >> 6) * 16;
    float acc[16];
    #pragma unroll
    for (int i = 0; i < 16; i++) acc[i] = 0.f;
    #pragma unroll 4
    for (int c = 0; c < CC; c++) {
        float w = W1sT[c][e];
        #pragma unroll
        for (int i = 0; i < 16; i++) acc[i] = fmaf(w, xs[c][nb+i], acc[i]);
    }
    #pragma unroll
    for (int i = 0; i < 16; i++)
        g_y1t[(b*NN + n0 + nb + i)*EE + e] = acc[i];
}

// BN1 stats over d = y_j - y_n (float4 gathers, idx shared via shfl)
// 32 points per CTA, grid 1024 for better latency hiding.
__global__ void k_stats1(const int* __restrict__ idx) {
    __shared__ float4 red_s[16][16];
    __shared__ float4 red_q[16][16];
    int t = threadIdx.x;
    int c4 = t & 15, g = t >> 4;       // 16 groups of 16 threads (half-warps)
    float4 s = make_float4(0.f,0.f,0.f,0.f);
    float4 q = make_float4(0.f,0.f,0.f,0.f);
    int p0 = blockIdx.x * 32;
    #pragma unroll
    for (int pl = 0; pl < 2; pl++) {
        int point = p0 + g*2 + pl;
        int brow = point & ~(NN-1);
        int jown = idx[point*KK + c4];   // lane c4 holds neighbor k=c4
        float4 yn = *(const float4*)(g_y1t + (size_t)point*EE + c4*4);
        #pragma unroll
        for (int k = 0; k < KK; k++) {
            int j = __shfl_sync(0xffffffffu, jown, ((t & 31) & 16) | k, 32);
            float4 yj = *(const float4*)(g_y1t + (size_t)(brow + j)*EE + c4*4);
            float dx = yj.x - yn.x, dy = yj.y - yn.y, dz = yj.z - yn.z, dw = yj.w - yn.w;
            s.x += dx; s.y += dy; s.z += dz; s.w += dw;
            q.x = fmaf(dx, dx, q.x); q.y = fmaf(dy, dy, q.y);
            q.z = fmaf(dz, dz, q.z); q.w = fmaf(dw, dw, q.w);
        }
    }
    red_s[g][c4] = s;
    red_q[g][c4] = q;
    __syncthreads();
    if (t < 64) {
        float ss = 0.f, qq = 0.f;
        #pragma unroll
        for (int gg = 0; gg < 16; gg++) {
            ss += ((const float*)&red_s[gg][t >> 2])[t & 3];
            qq += ((const float*)&red_q[gg][t >> 2])[t & 3];
        }
        atomicAdd(&g_sum1[t], ss);
        atomicAdd(&g_sumsq1[t], qq);
    }
}

// fold BN1 into y with CHANNEL PERMUTATION:
// phys float4 slot (blk, q) holds orig channels {blk*16+2q, +1, blk*16+2q+8, +9}
__global__ void k_prep(const float* __restrict__ g1, const float* __restrict__ be1) {
    int i = blockIdx.x * blockDim.x + threadIdx.x;   // phys float4 id, 524288 total
    int point = i >> 4;
    int blk = (i >> 2) & 3;
    int q = i & 3;
    int cb = blk*16 + q*2;
    int co[4] = {cb, cb+1, cb+8, cb+9};
    float a[4], cv[4];
    #pragma unroll
    for (int j = 0; j < 4; j++) {
        int c = co[j];
        float m1 = g_sum1[c] * (1.f/CNT1);
        float v1 = fmaxf(g_sumsq1[c] * (1.f/CNT1) - m1*m1, 0.f);
        a[j] = g1[c] * rsqrtf(v1 + EPSV);
        cv[j] = be1[c] - a[j] * m1;
    }
    const float* yrow = g_y1t + (size_t)point*EE + blk*16;
    float2 A = *(const float2*)(yrow + q*2);
    float2 B = *(const float2*)(yrow + q*2 + 8);
    float4 u;
    u.x = A.x*a[0]; u.y = A.y*a[1]; u.z = B.x*a[2]; u.w = B.y*a[3];
    float4 un;
    un.x = u.x - cv[0]; un.y = u.y - cv[1]; un.z = u.z - cv[2]; un.w = u.w - cv[3];
    ((float4*)g_u)[i]  = u;
    ((float4*)g_un)[i] = un;
}

// ============================================================================
// Main pass via mma.sync bf16 (split-bf16, 3 terms), operand-swapped,
// with cp.async.cg double-buffered THREAD-LOCAL gather staging.
#define EDGE_STAGE_BYTES (12*512)              // 6 KB per stage
#define EDGE_WARP_BYTES  (2*EDGE_STAGE_BYTES)  // 12 KB per warp
#define EDGE_SMEM (4*EDGE_WARP_BYTES + 512)    // 49664 B

__device__ __forceinline__ void stage_point(uint32_t dlane, int qoff,
                                            int p, int j0, int j1) {
    int base = p & ~(NN-1);
    const char* cen = (const char*)g_un + (((size_t)p) << 8) + qoff;
    const char* r0  = (const char*)g_u  + (((size_t)(base + j0)) << 8) + qoff;
    const char* r1  = (const char*)g_u  + (((size_t)(base + j1)) << 8) + qoff;
    #pragma unroll
    for (int ks = 0; ks < 4; ks++) {
        CP16(dlane + (ks*3+0)*512, cen + ks*64);
        CP16(dlane + (ks*3+1)*512, r0  + ks*64);
        CP16(dlane + (ks*3+2)*512, r1  + ks*64);
    }
    CP_COMMIT();
}

__global__ void __launch_bounds__(128, 4) k_edge(const int* __restrict__ idx,
                                                 const float* __restrict__ W2) {
    extern __shared__ char esm[];
    float* sm_s = (float*)(esm + 4*EDGE_WARP_BYTES);
    float* sm_q = sm_s + 64;
    int t = threadIdx.x;
    int lane = t & 31, w = t >> 5;
    int g = lane >> 2, q = lane & 3;

    if (t < 64) { sm_s[t] = 0.f; sm_q[t] = 0.f; }

    // A = W2 fragments for this warp's 2 m-tiles (32 output channels), resident
    int mtb = (w & 1) * 2;
    uint32_t Ahi[2][4][4], Alo[2][4][4];
    #pragma unroll
    for (int mi = 0; mi < 2; mi++) {
        int o0 = (mtb + mi)*16 + g;
        #pragma unroll
        for (int ks = 0; ks < 4; ks++) {
            int cb = ks*16 + q*2;
            const float* r0 = W2 + o0*64 + cb;
            const float* r1 = W2 + (o0+8)*64 + cb;
            float2 a00 = *(const float2*)(r0);
            float2 a01 = *(const float2*)(r0 + 8);
            float2 a10 = *(const float2*)(r1);
            float2 a11 = *(const float2*)(r1 + 8);
            split2(a00.x, a00.y, Ahi[mi][ks][0], Alo[mi][ks][0]);
            split2(a10.x, a10.y, Ahi[mi][ks][1], Alo[mi][ks][1]);
            split2(a01.x, a01.y, Ahi[mi][ks][2], Alo[mi][ks][2]);
            split2(a11.x, a11.y, Ahi[mi][ks][3], Alo[mi][ks][3]);
        }
    }

    uint32_t dlane = smem_u32(esm) + w*EDGE_WARP_BYTES + lane*16;
    int qoff = q*16;
    int pslot = w >> 1;
    int pbase = blockIdx.x * 16 + pslot * 8;

    float sums[4], sumq[4];
    #pragma unroll
    for (int i = 0; i < 4; i++) { sums[i] = 0.f; sumq[i] = 0.f; }

    // prologue: stage point 0, prefetch idx for point 1
    int j0c = idx[pbase*KK + g],       j1c = idx[pbase*KK + 8 + g];
    int j0n = idx[(pbase+1)*KK + g],   j1n = idx[(pbase+1)*KK + 8 + g];
    stage_point(dlane, qoff, pbase, j0c, j1c);

    __syncthreads();   // sm_s/sm_q init visible before end-of-kernel atomics

    #pragma unroll 1
    for (int pi = 0; pi < 8; pi++) {
        int p = pbase + pi;
        uint32_t buf = dlane + (pi & 1) * EDGE_STAGE_BYTES;
        CP_WAIT0();                          // buf(pi) ready (staged last iter)

        // prefetch idx for pi+2 (clamped; covered by this point's MMA latency)
        int pn2 = pbase + ((pi + 2 < 8) ? pi + 2 : 7);
        int j0f = idx[pn2*KK + g], j1f = idx[pn2*KK + 8 + g];
        // stage pi+1 into the other buffer; flies during MMA+epilogue below
        if (pi < 7)
            stage_point(dlane + ((pi+1) & 1) * EDGE_STAGE_BYTES, qoff, p + 1, j0n, j1n);

        float D[2][2][4];
        #pragma unroll
        for (int mi = 0; mi < 2; mi++)
            #pragma unroll
            for (int nt = 0; nt < 2; nt++)
                #pragma unroll
                for (int i = 0; i < 4; i++) D[mi][nt][i] = 0.f;

        #pragma unroll
        for (int ks = 0; ks < 4; ks++) {
            float4 nf = lds128(buf + (ks*3+0)*512);
            float4 x0 = lds128(buf + (ks*3+1)*512);
            float4 x1 = lds128(buf + (ks*3+2)*512);
            uint32_t bh00, bl00, bh01, bl01;
            uint32_t bh10, bl10, bh11, bl11;
            split2(fmaxf(x0.x - nf.x, 0.f), fmaxf(x0.y - nf.y, 0.f), bh00, bl00);
            split2(fmaxf(x0.z - nf.z, 0.f), fmaxf(x0.w - nf.w, 0.f), bh01, bl01);
            split2(fmaxf(x1.x - nf.x, 0.f), fmaxf(x1.y - nf.y, 0.f), bh10, bl10);
            split2(fmaxf(x1.z - nf.z, 0.f), fmaxf(x1.w - nf.w, 0.f), bh11, bl11);
            #pragma unroll
            for (int mi = 0; mi < 2; mi++) {
                mma16816(D[mi][0], Ahi[mi][ks], bh00, bh01);
                mma16816(D[mi][0], Alo[mi][ks], bh00, bh01);
                mma16816(D[mi][0], Ahi[mi][ks], bl00, bl01);
                mma16816(D[mi][1], Ahi[mi][ks], bh10, bh11);
                mma16816(D[mi][1], Alo[mi][ks], bh10, bh11);
                mma16816(D[mi][1], Ahi[mi][ks], bl10, bl11);
            }
        }

        // reduce over neighbors: in-thread, then shfl over q
        #pragma unroll
        for (int mi = 0; mi < 2; mi++) {
            float d00 = D[mi][0][0], d01 = D[mi][0][1];
            float d10 = D[mi][1][0], d11 = D[mi][1][1];
            float e00 = D[mi][0][2], e01 = D[mi][0][3];
            float e10 = D[mi][1][2], e11 = D[mi][1][3];
            sums[mi*2]   += (d00 + d01) + (d10 + d11);
            sums[mi*2+1] += (e00 + e01) + (e10 + e11);
            sumq[mi*2]   = fmaf(d00,d00, fmaf(d01,d01, fmaf(d10,d10, fmaf(d11,d11, sumq[mi*2]))));
            sumq[mi*2+1] = fmaf(e00,e00, fmaf(e01,e01, fmaf(e10,e10, fmaf(e11,e11, sumq[mi*2+1]))));
            float mx0 = fmaxf(fmaxf(d00, d01), fmaxf(d10, d11));
            float mn0 = fminf(fminf(d00, d01), fminf(d10, d11));
            float mx1 = fmaxf(fmaxf(e00, e01), fmaxf(e10, e11));
            float mn1 = fminf(fminf(e00, e01), fminf(e10, e11));
            #pragma unroll
            for (int off = 1; off < 4; off <<= 1) {
                mx0 = fmaxf(mx0, __shfl_xor_sync(0xffffffffu, mx0, off));
                mn0 = fminf(mn0, __shfl_xor_sync(0xffffffffu, mn0, off));
                mx1 = fmaxf(mx1, __shfl_xor_sync(0xffffffffu, mx1, off));
                mn1 = fminf(mn1, __shfl_xor_sync(0xffffffffu, mn1, off));
            }
            if (q == 0) {
                int ch = (mtb + mi)*16 + g;
                g_zmax[(size_t)p*EE + ch]     = mx0;
                g_zmax[(size_t)p*EE + ch + 8] = mx1;
                g_zmin[(size_t)p*EE + ch]     = mn0;
                g_zmin[(size_t)p*EE + ch + 8] = mn1;
            }
        }
        j0n = j0f; j1n = j1f;
    }

    // BN2 sums: shfl-reduce over q, stage in smem, one global atomic per channel
    #pragma unroll
    for (int i = 0; i < 4; i++) {
        float s = sums[i], qq = sumq[i];
        #pragma unroll
        for (int off = 1; off < 4; off <<= 1) {
            s  += __shfl_xor_sync(0xffffffffu, s, off);
            qq += __shfl_xor_sync(0xffffffffu, qq, off);
        }
        if (q == 0) {
            int ch = (mtb + (i >> 1))*16 + g + (i & 1)*8;
            atomicAdd(&sm_s[ch], s);
            atomicAdd(&sm_q[ch], qq);
        }
    }
    __syncthreads();
    if (t < 64) {
        atomicAdd(&g_sum2[t],   sm_s[t]);
        atomicAdd(&g_sumsq2[t], sm_q[t]);
    }
}

// ============================================================================
// pooled m = relu(a2*z_sel+c2); z3 = W3@m -> out
// 32 points per CTA, grid (128, 8) = 1024 CTAs for better occupancy/tail.
__global__ void k_pool3(const float* __restrict__ W3,
                        const float* __restrict__ g2,
                        const float* __restrict__ be2,
                        float* __restrict__ out) {
    __shared__ float ms[32][65];
    __shared__ float W3sT[CC][EE];
    int b = blockIdx.y;
    int n0 = blockIdx.x * 32;
    int t = threadIdx.x;
    for (int i = t; i < CC*EE; i += 256) {
        int o = i >> 6, c = i & 63;
        W3sT[c][o] = W3[i];
    }
    {
        int o = t & 63;
        int ng = t >> 6;
        float m2 = g_sum2[o] * (1.f/CNT1);
        float v2 = fmaxf(g_sumsq2[o] * (1.f/CNT1) - m2*m2, 0.f);
        float a2o = g2[o] * rsqrtf(v2 + EPSV);
        float c2o = be2[o] - a2o * m2;
        const float* zsel = (a2o >= 0.f) ? g_zmax : g_zmin;
        #pragma unroll
        for (int nl = ng; nl < 32; nl += 4) {
            int point = b*NN + n0 + nl;
            float zm = zsel[point*EE + o];
            ms[nl][o] = fmaxf(fmaf(a2o, zm, c2o), 0.f);
        }
    }
    __syncthreads();
    int nl = t & 31;
    int ob = (t >> 5) * 8;
    float acc[8];
    #pragma unroll
    for (int i = 0; i < 8; i++) acc[i] = 0.f;
    #pragma unroll 8
    for (int c = 0; c < CC; c++) {
        float mv = ms[nl][c];
        #pragma unroll
        for (int i = 0; i < 8; i++)
            acc[i] = fmaf(W3sT[c][ob+i], mv, acc[i]);
    }
    #pragma unroll
    for (int i = 0; i < 8; i++)
        out[(b*EE + ob + i)*NN + n0 + nl] = acc[i];
}

// BN3 stats over out
__global__ void k_stats3(const float* __restrict__ out) {
    __shared__ float r1[256], r2[256];
    int p = blockIdx.x;
    int o = p & 63;
    const float* base = out + (size_t)p*NN;
    int t = threadIdx.x;
    float s = 0.f, q = 0.f;
    for (int i = t; i < NN; i += 256) {
        float v = base[i];
        s += v;
        q = fmaf(v, v, q);
    }
    r1[t] = s; r2[t] = q;
    __syncthreads();
    for (int w = 128; w > 0; w >>= 1) {
        if (t < w) { r1[t] += r1[t+w]; r2[t] += r2[t+w]; }
        __syncthreads();
    }
    if (t == 0) {
        atomicAdd(&g_sum3[o], r1[0]);
        atomicAdd(&g_sumsq3[o], r2[0]);
    }
}

// BN3 + ReLU in place
__global__ void k_out(const float* __restrict__ g3, const float* __restrict__ be3,
                      float* __restrict__ out) {
    __shared__ float sa[EE], sc[EE];
    int t = threadIdx.x;
    if (t < EE) {
        float m3 = g_sum3[t] * (1.f/CNT3);
        float v3 = fmaxf(g_sumsq3[t] * (1.f/CNT3) - m3*m3, 0.f);
        float a3 = g3[t] * rsqrtf(v3 + EPSV);
        sa[t] = a3;
        sc[t] = be3[t] - a3 * m3;
    }
    __syncthreads();
    int gi = blockIdx.x * blockDim.x + t;
    int o = (gi >> 10) & 63;
    float4* out4 = (float4*)out;
    float4 v = out4[gi];
    float a = sa[o], c = sc[o];
    v.x = fmaxf(fmaf(a, v.x, c), 0.f);
    v.y = fmaxf(fmaf(a, v.y, c), 0.f);
    v.z = fmaxf(fmaf(a, v.z, c), 0.f);
    v.w = fmaxf(fmaf(a, v.w, c), 0.f);
    out4[gi] = v;
}

extern "C" void kernel_launch(void* const* d_in, const int* in_sizes, int n_in,
                              void* d_out, int out_size) {
    const float* x   = (const float*)d_in[0];
    const int*   idx = (const int*)  d_in[1];
    const float* W1  = (const float*)d_in[2];
    const float* g1  = (const float*)d_in[4];
    const float* be1 = (const float*)d_in[5];
    const float* W2  = (const float*)d_in[6];
    const float* g2  = (const float*)d_in[8];
    const float* be2 = (const float*)d_in[9];
    const float* W3  = (const float*)d_in[10];
    const float* g3  = (const float*)d_in[12];
    const float* be3 = (const float*)d_in[13];
    float* out = (float*)d_out;

    cudaFuncSetAttribute(k_edge, cudaFuncAttributeMaxDynamicSharedMemorySize, EDGE_SMEM);

    k_y1    <<<dim3(64, 8), 256>>>(x, W1);
    k_stats1<<<1024, 256>>>(idx);
    k_prep  <<<2048, 256>>>(g1, be1);
    k_edge  <<<2048, 128, EDGE_SMEM>>>(idx, W2);
    k_pool3 <<<dim3(128, 8), 256>>>(W3, g2, be2, out);
    k_stats3<<<512, 256>>>(out);
    k_out   <<<2048, 256>>>(g3, be3, out);
}

// round 11
// speedup vs baseline: 1.0141x; 1.0141x over previous
#include <cuda_runtime.h>
#include <cuda_bf16.h>
#include <cstdint>

#define BB 8
#define CC 64
#define NN 4096
#define KK 16
#define EE 64
#define NPOINTS (BB*NN)            // 32768
#define CNT1 524288.0f             // B*N*K
#define CNT3 32768.0f              // B*N
#define EPSV 1e-5f

// ---- scratch (device globals: allocation-free rule) ----
__device__ float g_y1t[NPOINTS*EE];       // 8 MB  raw y1 transposed [point][c]
__device__ float g_u[NPOINTS*EE];         // 8 MB  permuted u = a1*y
__device__ float g_un[NPOINTS*EE];        // 8 MB  permuted un' = u - c1
__device__ float g_zmax[NPOINTS*EE];      // 8 MB
__device__ float g_zmin[NPOINTS*EE];      // 8 MB
__device__ float g_sum1[EE], g_sumsq1[EE];
__device__ float g_sum2[EE], g_sumsq2[EE];
__device__ float g_bs3[32][128];          // BN3 bucketed partials: [bucket][0:64]=sum, [64:128]=sumsq

// pack two fp32 into bf16x2 (first arg -> low half)
__device__ __forceinline__ uint32_t pack_bf2(float lo_e, float hi_e) {
    uint32_t r;
    asm("cvt.rn.bf16x2.f32 %0, %1, %2;" : "=r"(r) : "f"(hi_e), "f"(lo_e));
    return r;
}

__device__ __forceinline__ void mma16816(float d[4], const uint32_t a[4], uint32_t b0, uint32_t b1) {
    asm volatile(
        "mma.sync.aligned.m16n8k16.row.col.f32.bf16.bf16.f32 "
        "{%0,%1,%2,%3}, {%4,%5,%6,%7}, {%8,%9}, {%0,%1,%2,%3};"
        : "+f"(d[0]), "+f"(d[1]), "+f"(d[2]), "+f"(d[3])
        : "r"(a[0]), "r"(a[1]), "r"(a[2]), "r"(a[3]), "r"(b0), "r"(b1));
}

// split a packed pair (x,y) into hi (bf16) and lo (residual bf16)
__device__ __forceinline__ void split2(float x, float y, uint32_t& hi, uint32_t& lo) {
    hi = pack_bf2(x, y);
    float e0 = __uint_as_float(hi << 16);
    float e1 = __uint_as_float(hi & 0xffff0000u);
    lo = pack_bf2(x - e0, y - e1);
}

__device__ __forceinline__ uint32_t smem_u32(const void* p) {
    uint32_t a;
    asm("{ .reg .u64 t; cvta.to.shared.u64 t, %1; cvt.u32.u64 %0, t; }" : "=r"(a) : "l"(p));
    return a;
}
__device__ __forceinline__ float4 lds128(uint32_t a) {
    float4 v;
    asm volatile("ld.shared.v4.f32 {%0,%1,%2,%3}, [%4];"
                 : "=f"(v.x), "=f"(v.y), "=f"(v.z), "=f"(v.w) : "r"(a));
    return v;
}
#define CP16(d, s) asm volatile("cp.async.cg.shared.global [%0], [%1], 16;" :: "r"(d), "l"(s) : "memory")
#define CP_COMMIT() asm volatile("cp.async.commit_group;" ::: "memory")
#define CP_WAIT0()  asm volatile("cp.async.wait_group 0;" ::: "memory")

// ============================================================================
// y1t[b][n][e] = sum_c W1[e][c] * x[b][c][n];  block(0,0) zeroes accumulators
__global__ void k_y1(const float* __restrict__ x, const float* __restrict__ W1) {
    __shared__ float xs[CC][64];
    __shared__ float W1sT[CC][EE];
    int b = blockIdx.y;
    int n0 = blockIdx.x * 64;
    int t = threadIdx.x;
    if (blockIdx.x == 0 && blockIdx.y == 0) {
        if (t < EE) {
            g_sum1[t]=0.f; g_sumsq1[t]=0.f;
            g_sum2[t]=0.f; g_sumsq2[t]=0.f;
        }
        for (int i = t; i < 32*128; i += 256) ((float*)g_bs3)[i] = 0.f;
    }
    for (int i = t; i < CC*EE; i += 256) {
        int o = i >> 6, c = i & 63;
        W1sT[c][o] = W1[i];
    }
    for (int i = t; i < CC*64; i += 256) {
        int c = i >> 6, j = i & 63;
        xs[c][j] = x[(b*CC + c)*NN + n0 + j];
    }
    __syncthreads();
    int e = t & 63;
    int nb = (t >> 6) * 16;
    float acc[16];
    #pragma unroll
    for (int i = 0; i < 16; i++) acc[i] = 0.f;
    #pragma unroll 4
    for (int c = 0; c < CC; c++) {
        float w = W1sT[c][e];
        #pragma unroll
        for (int i = 0; i < 16; i++) acc[i] = fmaf(w, xs[c][nb+i], acc[i]);
    }
    #pragma unroll
    for (int i = 0; i < 16; i++)
        g_y1t[(b*NN + n0 + nb + i)*EE + e] = acc[i];
}

// BN1 stats over d = y_j - y_n (float4 gathers, idx shared via shfl) — r9 shape
__global__ void k_stats1(const int* __restrict__ idx) {
    __shared__ float4 red_s[16][16];
    __shared__ float4 red_q[16][16];
    int t = threadIdx.x;
    int c4 = t & 15, g = t >> 4;       // 16 groups of 16 threads (half-warps)
    float4 s = make_float4(0.f,0.f,0.f,0.f);
    float4 q = make_float4(0.f,0.f,0.f,0.f);
    int p0 = blockIdx.x * 64;
    #pragma unroll 1
    for (int pl = 0; pl < 4; pl++) {
        int point = p0 + g*4 + pl;
        int brow = point & ~(NN-1);
        int jown = idx[point*KK + c4];   // lane c4 holds neighbor k=c4
        float4 yn = *(const float4*)(g_y1t + (size_t)point*EE + c4*4);
        #pragma unroll
        for (int k = 0; k < KK; k++) {
            int j = __shfl_sync(0xffffffffu, jown, ((t & 31) & 16) | k, 32);
            float4 yj = *(const float4*)(g_y1t + (size_t)(brow + j)*EE + c4*4);
            float dx = yj.x - yn.x, dy = yj.y - yn.y, dz = yj.z - yn.z, dw = yj.w - yn.w;
            s.x += dx; s.y += dy; s.z += dz; s.w += dw;
            q.x = fmaf(dx, dx, q.x); q.y = fmaf(dy, dy, q.y);
            q.z = fmaf(dz, dz, q.z); q.w = fmaf(dw, dw, q.w);
        }
    }
    red_s[g][c4] = s;
    red_q[g][c4] = q;
    __syncthreads();
    if (t < 64) {
        float ss = 0.f, qq = 0.f;
        #pragma unroll
        for (int gg = 0; gg < 16; gg++) {
            ss += ((const float*)&red_s[gg][t >> 2])[t & 3];
            qq += ((const float*)&red_q[gg][t >> 2])[t & 3];
        }
        atomicAdd(&g_sum1[t], ss);
        atomicAdd(&g_sumsq1[t], qq);
    }
}

// fold BN1 into y with CHANNEL PERMUTATION:
// phys float4 slot (blk, q) holds orig channels {blk*16+2q, +1, blk*16+2q+8, +9}
__global__ void k_prep(const float* __restrict__ g1, const float* __restrict__ be1) {
    int i = blockIdx.x * blockDim.x + threadIdx.x;   // phys float4 id, 524288 total
    int point = i >> 4;
    int blk = (i >> 2) & 3;
    int q = i & 3;
    int cb = blk*16 + q*2;
    int co[4] = {cb, cb+1, cb+8, cb+9};
    float a[4], cv[4];
    #pragma unroll
    for (int j = 0; j < 4; j++) {
        int c = co[j];
        float m1 = g_sum1[c] * (1.f/CNT1);
        float v1 = fmaxf(g_sumsq1[c] * (1.f/CNT1) - m1*m1, 0.f);
        a[j] = g1[c] * rsqrtf(v1 + EPSV);
        cv[j] = be1[c] - a[j] * m1;
    }
    const float* yrow = g_y1t + (size_t)point*EE + blk*16;
    float2 A = *(const float2*)(yrow + q*2);
    float2 B = *(const float2*)(yrow + q*2 + 8);
    float4 u;
    u.x = A.x*a[0]; u.y = A.y*a[1]; u.z = B.x*a[2]; u.w = B.y*a[3];
    float4 un;
    un.x = u.x - cv[0]; un.y = u.y - cv[1]; un.z = u.z - cv[2]; un.w = u.w - cv[3];
    ((float4*)g_u)[i]  = u;
    ((float4*)g_un)[i] = un;
}

// ============================================================================
// Main pass via mma.sync bf16 (split-bf16, 3 terms), operand-swapped,
// with cp.async.cg double-buffered THREAD-LOCAL gather staging.
#define EDGE_STAGE_BYTES (12*512)              // 6 KB per stage
#define EDGE_WARP_BYTES  (2*EDGE_STAGE_BYTES)  // 12 KB per warp
#define EDGE_SMEM (4*EDGE_WARP_BYTES + 512)    // 49664 B

__device__ __forceinline__ void stage_point(uint32_t dlane, int qoff,
                                            int p, int j0, int j1) {
    int base = p & ~(NN-1);
    const char* cen = (const char*)g_un + (((size_t)p) << 8) + qoff;
    const char* r0  = (const char*)g_u  + (((size_t)(base + j0)) << 8) + qoff;
    const char* r1  = (const char*)g_u  + (((size_t)(base + j1)) << 8) + qoff;
    #pragma unroll
    for (int ks = 0; ks < 4; ks++) {
        CP16(dlane + (ks*3+0)*512, cen + ks*64);
        CP16(dlane + (ks*3+1)*512, r0  + ks*64);
        CP16(dlane + (ks*3+2)*512, r1  + ks*64);
    }
    CP_COMMIT();
}

__global__ void __launch_bounds__(128, 4) k_edge(const int* __restrict__ idx,
                                                 const float* __restrict__ W2) {
    extern __shared__ char esm[];
    float* sm_s = (float*)(esm + 4*EDGE_WARP_BYTES);
    float* sm_q = sm_s + 64;
    int t = threadIdx.x;
    int lane = t & 31, w = t >> 5;
    int g = lane >> 2, q = lane & 3;

    if (t < 64) { sm_s[t] = 0.f; sm_q[t] = 0.f; }

    // A = W2 fragments for this warp's 2 m-tiles (32 output channels), resident
    int mtb = (w & 1) * 2;
    uint32_t Ahi[2][4][4], Alo[2][4][4];
    #pragma unroll
    for (int mi = 0; mi < 2; mi++) {
        int o0 = (mtb + mi)*16 + g;
        #pragma unroll
        for (int ks = 0; ks < 4; ks++) {
            int cb = ks*16 + q*2;
            const float* r0 = W2 + o0*64 + cb;
            const float* r1 = W2 + (o0+8)*64 + cb;
            float2 a00 = *(const float2*)(r0);
            float2 a01 = *(const float2*)(r0 + 8);
            float2 a10 = *(const float2*)(r1);
            float2 a11 = *(const float2*)(r1 + 8);
            split2(a00.x, a00.y, Ahi[mi][ks][0], Alo[mi][ks][0]);
            split2(a10.x, a10.y, Ahi[mi][ks][1], Alo[mi][ks][1]);
            split2(a01.x, a01.y, Ahi[mi][ks][2], Alo[mi][ks][2]);
            split2(a11.x, a11.y, Ahi[mi][ks][3], Alo[mi][ks][3]);
        }
    }

    uint32_t dlane = smem_u32(esm) + w*EDGE_WARP_BYTES + lane*16;
    int qoff = q*16;
    int pslot = w >> 1;
    int pbase = blockIdx.x * 16 + pslot * 8;

    float sums[4], sumq[4];
    #pragma unroll
    for (int i = 0; i < 4; i++) { sums[i] = 0.f; sumq[i] = 0.f; }

    // prologue: stage point 0, prefetch idx for point 1
    int j0c = idx[pbase*KK + g],       j1c = idx[pbase*KK + 8 + g];
    int j0n = idx[(pbase+1)*KK + g],   j1n = idx[(pbase+1)*KK + 8 + g];
    stage_point(dlane, qoff, pbase, j0c, j1c);

    __syncthreads();   // sm_s/sm_q init visible before end-of-kernel atomics

    #pragma unroll 1
    for (int pi = 0; pi < 8; pi++) {
        int p = pbase + pi;
        uint32_t buf = dlane + (pi & 1) * EDGE_STAGE_BYTES;
        CP_WAIT0();                          // buf(pi) ready (staged last iter)

        // prefetch idx for pi+2 (clamped; covered by this point's MMA latency)
        int pn2 = pbase + ((pi + 2 < 8) ? pi + 2 : 7);
        int j0f = idx[pn2*KK + g], j1f = idx[pn2*KK + 8 + g];
        // stage pi+1 into the other buffer; flies during MMA+epilogue below
        if (pi < 7)
            stage_point(dlane + ((pi+1) & 1) * EDGE_STAGE_BYTES, qoff, p + 1, j0n, j1n);

        float D[2][2][4];
        #pragma unroll
        for (int mi = 0; mi < 2; mi++)
            #pragma unroll
            for (int nt = 0; nt < 2; nt++)
                #pragma unroll
                for (int i = 0; i < 4; i++) D[mi][nt][i] = 0.f;

        #pragma unroll
        for (int ks = 0; ks < 4; ks++) {
            float4 nf = lds128(buf + (ks*3+0)*512);
            float4 x0 = lds128(buf + (ks*3+1)*512);
            float4 x1 = lds128(buf + (ks*3+2)*512);
            uint32_t bh00, bl00, bh01, bl01;
            uint32_t bh10, bl10, bh11, bl11;
            split2(fmaxf(x0.x - nf.x, 0.f), fmaxf(x0.y - nf.y, 0.f), bh00, bl00);
            split2(fmaxf(x0.z - nf.z, 0.f), fmaxf(x0.w - nf.w, 0.f), bh01, bl01);
            split2(fmaxf(x1.x - nf.x, 0.f), fmaxf(x1.y - nf.y, 0.f), bh10, bl10);
            split2(fmaxf(x1.z - nf.z, 0.f), fmaxf(x1.w - nf.w, 0.f), bh11, bl11);
            #pragma unroll
            for (int mi = 0; mi < 2; mi++) {
                mma16816(D[mi][0], Ahi[mi][ks], bh00, bh01);
                mma16816(D[mi][0], Alo[mi][ks], bh00, bh01);
                mma16816(D[mi][0], Ahi[mi][ks], bl00, bl01);
                mma16816(D[mi][1], Ahi[mi][ks], bh10, bh11);
                mma16816(D[mi][1], Alo[mi][ks], bh10, bh11);
                mma16816(D[mi][1], Ahi[mi][ks], bl10, bl11);
            }
        }

        // reduce over neighbors: in-thread, then shfl over q
        #pragma unroll
        for (int mi = 0; mi < 2; mi++) {
            float d00 = D[mi][0][0], d01 = D[mi][0][1];
            float d10 = D[mi][1][0], d11 = D[mi][1][1];
            float e00 = D[mi][0][2], e01 = D[mi][0][3];
            float e10 = D[mi][1][2], e11 = D[mi][1][3];
            sums[mi*2]   += (d00 + d01) + (d10 + d11);
            sums[mi*2+1] += (e00 + e01) + (e10 + e11);
            sumq[mi*2]   = fmaf(d00,d00, fmaf(d01,d01, fmaf(d10,d10, fmaf(d11,d11, sumq[mi*2]))));
            sumq[mi*2+1] = fmaf(e00,e00, fmaf(e01,e01, fmaf(e10,e10, fmaf(e11,e11, sumq[mi*2+1]))));
            float mx0 = fmaxf(fmaxf(d00, d01), fmaxf(d10, d11));
            float mn0 = fminf(fminf(d00, d01), fminf(d10, d11));
            float mx1 = fmaxf(fmaxf(e00, e01), fmaxf(e10, e11));
            float mn1 = fminf(fminf(e00, e01), fminf(e10, e11));
            #pragma unroll
            for (int off = 1; off < 4; off <<= 1) {
                mx0 = fmaxf(mx0, __shfl_xor_sync(0xffffffffu, mx0, off));
                mn0 = fminf(mn0, __shfl_xor_sync(0xffffffffu, mn0, off));
                mx1 = fmaxf(mx1, __shfl_xor_sync(0xffffffffu, mx1, off));
                mn1 = fminf(mn1, __shfl_xor_sync(0xffffffffu, mn1, off));
            }
            if (q == 0) {
                int ch = (mtb + mi)*16 + g;
                g_zmax[(size_t)p*EE + ch]     = mx0;
                g_zmax[(size_t)p*EE + ch + 8] = mx1;
                g_zmin[(size_t)p*EE + ch]     = mn0;
                g_zmin[(size_t)p*EE + ch + 8] = mn1;
            }
        }
        j0n = j0f; j1n = j1f;
    }

    // BN2 sums: shfl-reduce over q, stage in smem, one global atomic per channel
    #pragma unroll
    for (int i = 0; i < 4; i++) {
        float s = sums[i], qq = sumq[i];
        #pragma unroll
        for (int off = 1; off < 4; off <<= 1) {
            s  += __shfl_xor_sync(0xffffffffu, s, off);
            qq += __shfl_xor_sync(0xffffffffu, qq, off);
        }
        if (q == 0) {
            int ch = (mtb + (i >> 1))*16 + g + (i & 1)*8;
            atomicAdd(&sm_s[ch], s);
            atomicAdd(&sm_q[ch], qq);
        }
    }
    __syncthreads();
    if (t < 64) {
        atomicAdd(&g_sum2[t],   sm_s[t]);
        atomicAdd(&g_sumsq2[t], sm_q[t]);
    }
}

// ============================================================================
// pooled m = relu(a2*z_sel+c2); z3 = W3@m -> out; BN3 partials -> 32 buckets
// (r9 shape: grid (64,8), 64 points/CTA; shfl-reduce + bucketed atomics)
__global__ void k_pool3(const float* __restrict__ W3,
                        const float* __restrict__ g2,
                        const float* __restrict__ be2,
                        float* __restrict__ out) {
    __shared__ float ms[64][65];
    __shared__ float W3sT[CC][EE];
    int b = blockIdx.y;
    int n0 = blockIdx.x * 64;
    int t = threadIdx.x;
    for (int i = t; i < CC*EE; i += 256) {
        int o = i >> 6, c = i & 63;
        W3sT[c][o] = W3[i];
    }
    {
        int o = t & 63;
        int ng = t >> 6;
        float m2 = g_sum2[o] * (1.f/CNT1);
        float v2 = fmaxf(g_sumsq2[o] * (1.f/CNT1) - m2*m2, 0.f);
        float a2o = g2[o] * rsqrtf(v2 + EPSV);
        float c2o = be2[o] - a2o * m2;
        const float* zsel = (a2o >= 0.f) ? g_zmax : g_zmin;
        for (int nl = ng; nl < 64; nl += 4) {
            int point = b*NN + n0 + nl;
            float zm = zsel[point*EE + o];
            ms[nl][o] = fmaxf(fmaf(a2o, zm, c2o), 0.f);
        }
    }
    __syncthreads();
    int nl = t & 63;
    int ob = (t >> 6) * 16;
    float acc[16];
    #pragma unroll
    for (int i = 0; i < 16; i++) acc[i] = 0.f;
    #pragma unroll 4
    for (int c = 0; c < CC; c++) {
        float mv = ms[nl][c];
        #pragma unroll
        for (int i = 0; i < 16; i++)
            acc[i] = fmaf(W3sT[c][ob+i], mv, acc[i]);
    }
    #pragma unroll
    for (int i = 0; i < 16; i++)
        out[(b*EE + ob + i)*NN + n0 + nl] = acc[i];

    // BN3 partials: shfl-reduce over the 32 points in this warp, bucketed atomics
    int bucket = (blockIdx.y * 64 + blockIdx.x) & 31;
    #pragma unroll
    for (int i = 0; i < 16; i++) {
        float s = acc[i];
        float qv = acc[i] * acc[i];
        #pragma unroll
        for (int off = 16; off > 0; off >>= 1) {
            s  += __shfl_xor_sync(0xffffffffu, s, off);
            qv += __shfl_xor_sync(0xffffffffu, qv, off);
        }
        if ((t & 31) == 0) {
            atomicAdd(&g_bs3[bucket][ob + i], s);
            atomicAdd(&g_bs3[bucket][64 + ob + i], qv);
        }
    }
}

// BN3 + ReLU in place (folds the 32 buckets first)
__global__ void k_out(const float* __restrict__ g3, const float* __restrict__ be3,
                      float* __restrict__ out) {
    __shared__ float sa[EE], sc[EE];
    int t = threadIdx.x;
    if (t < EE) {
        float s = 0.f, qv = 0.f;
        #pragma unroll
        for (int bk = 0; bk < 32; bk++) {
            s  += g_bs3[bk][t];
            qv += g_bs3[bk][64 + t];
        }
        float m3 = s * (1.f/CNT3);
        float v3 = fmaxf(qv * (1.f/CNT3) - m3*m3, 0.f);
        float a3 = g3[t] * rsqrtf(v3 + EPSV);
        sa[t] = a3;
        sc[t] = be3[t] - a3 * m3;
    }
    __syncthreads();
    int gi = blockIdx.x * blockDim.x + t;
    int o = (gi >> 10) & 63;
    float4* out4 = (float4*)out;
    float4 v = out4[gi];
    float a = sa[o], c = sc[o];
    v.x = fmaxf(fmaf(a, v.x, c), 0.f);
    v.y = fmaxf(fmaf(a, v.y, c), 0.f);
    v.z = fmaxf(fmaf(a, v.z, c), 0.f);
    v.w = fmaxf(fmaf(a, v.w, c), 0.f);
    out4[gi] = v;
}

extern "C" void kernel_launch(void* const* d_in, const int* in_sizes, int n_in,
                              void* d_out, int out_size) {
    const float* x   = (const float*)d_in[0];
    const int*   idx = (const int*)  d_in[1];
    const float* W1  = (const float*)d_in[2];
    const float* g1  = (const float*)d_in[4];
    const float* be1 = (const float*)d_in[5];
    const float* W2  = (const float*)d_in[6];
    const float* g2  = (const float*)d_in[8];
    const float* be2 = (const float*)d_in[9];
    const float* W3  = (const float*)d_in[10];
    const float* g3  = (const float*)d_in[12];
    const float* be3 = (const float*)d_in[13];
    float* out = (float*)d_out;

    cudaFuncSetAttribute(k_edge, cudaFuncAttributeMaxDynamicSharedMemorySize, EDGE_SMEM);

    k_y1    <<<dim3(64, 8), 256>>>(x, W1);
    k_stats1<<<512, 256>>>(idx);
    k_prep  <<<2048, 256>>>(g1, be1);
    k_edge  <<<2048, 128, EDGE_SMEM>>>(idx, W2);
    k_pool3 <<<dim3(64, 8), 256>>>(W3, g2, be2, out);
    k_out   <<<2048, 256>>>(g3, be3, out);
}

// round 12
// speedup vs baseline: 1.0400x; 1.0255x over previous
#include <cuda_runtime.h>
#include <cuda_bf16.h>
#include <cstdint>

#define BB 8
#define CC 64
#define NN 4096
#define KK 16
#define EE 64
#define NPOINTS (BB*NN)            // 32768
#define CNT1 524288.0f             // B*N*K
#define CNT3 32768.0f              // B*N
#define EPSV 1e-5f

// ---- scratch (device globals: allocation-free rule) ----
__device__ float g_y1t[NPOINTS*EE];       // 8 MB  raw y1 transposed [point][c]
__device__ float g_u[NPOINTS*EE];         // 8 MB  permuted u = a1*y
__device__ float g_un[NPOINTS*EE];        // 8 MB  permuted un' = u - c1
__device__ float g_zmax[NPOINTS*EE];      // 8 MB
__device__ float g_zmin[NPOINTS*EE];      // 8 MB
__device__ float g_sum1[EE], g_sumsq1[EE];
__device__ float g_sum2[EE], g_sumsq2[EE];
__device__ float g_bs3[32][128];          // BN3 bucketed partials: [bucket][0:64]=sum, [64:128]=sumsq

// pack two fp32 into bf16x2 (first arg -> low half)
__device__ __forceinline__ uint32_t pack_bf2(float lo_e, float hi_e) {
    uint32_t r;
    asm("cvt.rn.bf16x2.f32 %0, %1, %2;" : "=r"(r) : "f"(hi_e), "f"(lo_e));
    return r;
}

__device__ __forceinline__ void mma16816(float d[4], const uint32_t a[4], uint32_t b0, uint32_t b1) {
    asm volatile(
        "mma.sync.aligned.m16n8k16.row.col.f32.bf16.bf16.f32 "
        "{%0,%1,%2,%3}, {%4,%5,%6,%7}, {%8,%9}, {%0,%1,%2,%3};"
        : "+f"(d[0]), "+f"(d[1]), "+f"(d[2]), "+f"(d[3])
        : "r"(a[0]), "r"(a[1]), "r"(a[2]), "r"(a[3]), "r"(b0), "r"(b1));
}

// split a packed pair (x,y) into hi (bf16) and lo (residual bf16)
__device__ __forceinline__ void split2(float x, float y, uint32_t& hi, uint32_t& lo) {
    hi = pack_bf2(x, y);
    float e0 = __uint_as_float(hi << 16);
    float e1 = __uint_as_float(hi & 0xffff0000u);
    lo = pack_bf2(x - e0, y - e1);
}

__device__ __forceinline__ uint32_t smem_u32(const void* p) {
    uint32_t a;
    asm("{ .reg .u64 t; cvta.to.shared.u64 t, %1; cvt.u32.u64 %0, t; }" : "=r"(a) : "l"(p));
    return a;
}
__device__ __forceinline__ float4 lds128(uint32_t a) {
    float4 v;
    asm volatile("ld.shared.v4.f32 {%0,%1,%2,%3}, [%4];"
                 : "=f"(v.x), "=f"(v.y), "=f"(v.z), "=f"(v.w) : "r"(a));
    return v;
}
#define CP16(d, s) asm volatile("cp.async.cg.shared.global [%0], [%1], 16;" :: "r"(d), "l"(s) : "memory")
#define CP_COMMIT() asm volatile("cp.async.commit_group;" ::: "memory")
#define CP_WAIT0()  asm volatile("cp.async.wait_group 0;" ::: "memory")

// ============================================================================
// y1t[b][n][e] = sum_c W1[e][c] * x[b][c][n];  block(0,0) zeroes accumulators
__global__ void k_y1(const float* __restrict__ x, const float* __restrict__ W1) {
    __shared__ float xs[CC][64];
    __shared__ float W1sT[CC][EE];
    int b = blockIdx.y;
    int n0 = blockIdx.x * 64;
    int t = threadIdx.x;
    if (blockIdx.x == 0 && blockIdx.y == 0) {
        if (t < EE) {
            g_sum1[t]=0.f; g_sumsq1[t]=0.f;
            g_sum2[t]=0.f; g_sumsq2[t]=0.f;
        }
        for (int i = t; i < 32*128; i += 256) ((float*)g_bs3)[i] = 0.f;
    }
    for (int i = t; i < CC*EE; i += 256) {
        int o = i >> 6, c = i & 63;
        W1sT[c][o] = W1[i];
    }
    for (int i = t; i < CC*64; i += 256) {
        int c = i >> 6, j = i & 63;
        xs[c][j] = x[(b*CC + c)*NN + n0 + j];
    }
    __syncthreads();
    int e = t & 63;
    int nb = (t >> 6) * 16;
    float acc[16];
    #pragma unroll
    for (int i = 0; i < 16; i++) acc[i] = 0.f;
    #pragma unroll 4
    for (int c = 0; c < CC; c++) {
        float w = W1sT[c][e];
        #pragma unroll
        for (int i = 0; i < 16; i++) acc[i] = fmaf(w, xs[c][nb+i], acc[i]);
    }
    #pragma unroll
    for (int i = 0; i < 16; i++)
        g_y1t[(b*NN + n0 + nb + i)*EE + e] = acc[i];
}

// BN1 stats over d = y_j - y_n (float4 gathers, idx shared via shfl)
__global__ void k_stats1(const int* __restrict__ idx) {
    __shared__ float4 red_s[16][16];
    __shared__ float4 red_q[16][16];
    int t = threadIdx.x;
    int c4 = t & 15, g = t >> 4;       // 16 groups of 16 threads (half-warps)
    float4 s = make_float4(0.f,0.f,0.f,0.f);
    float4 q = make_float4(0.f,0.f,0.f,0.f);
    int p0 = blockIdx.x * 64;
    #pragma unroll 1
    for (int pl = 0; pl < 4; pl++) {
        int point = p0 + g*4 + pl;
        int brow = point & ~(NN-1);
        int jown = idx[point*KK + c4];   // lane c4 holds neighbor k=c4
        float4 yn = *(const float4*)(g_y1t + (size_t)point*EE + c4*4);
        #pragma unroll
        for (int k = 0; k < KK; k++) {
            int j = __shfl_sync(0xffffffffu, jown, ((t & 31) & 16) | k, 32);
            float4 yj = *(const float4*)(g_y1t + (size_t)(brow + j)*EE + c4*4);
            float dx = yj.x - yn.x, dy = yj.y - yn.y, dz = yj.z - yn.z, dw = yj.w - yn.w;
            s.x += dx; s.y += dy; s.z += dz; s.w += dw;
            q.x = fmaf(dx, dx, q.x); q.y = fmaf(dy, dy, q.y);
            q.z = fmaf(dz, dz, q.z); q.w = fmaf(dw, dw, q.w);
        }
    }
    red_s[g][c4] = s;
    red_q[g][c4] = q;
    __syncthreads();
    if (t < 64) {
        float ss = 0.f, qq = 0.f;
        #pragma unroll
        for (int gg = 0; gg < 16; gg++) {
            ss += ((const float*)&red_s[gg][t >> 2])[t & 3];
            qq += ((const float*)&red_q[gg][t >> 2])[t & 3];
        }
        atomicAdd(&g_sum1[t], ss);
        atomicAdd(&g_sumsq1[t], qq);
    }
}

// fold BN1 into y with CHANNEL PERMUTATION:
// phys float4 slot (blk, q) holds orig channels {blk*16+2q, +1, blk*16+2q+8, +9}
__global__ void k_prep(const float* __restrict__ g1, const float* __restrict__ be1) {
    int i = blockIdx.x * blockDim.x + threadIdx.x;   // phys float4 id, 524288 total
    int point = i >> 4;
    int blk = (i >> 2) & 3;
    int q = i & 3;
    int cb = blk*16 + q*2;
    int co[4] = {cb, cb+1, cb+8, cb+9};
    float a[4], cv[4];
    #pragma unroll
    for (int j = 0; j < 4; j++) {
        int c = co[j];
        float m1 = g_sum1[c] * (1.f/CNT1);
        float v1 = fmaxf(g_sumsq1[c] * (1.f/CNT1) - m1*m1, 0.f);
        a[j] = g1[c] * rsqrtf(v1 + EPSV);
        cv[j] = be1[c] - a[j] * m1;
    }
    const float* yrow = g_y1t + (size_t)point*EE + blk*16;
    float2 A = *(const float2*)(yrow + q*2);
    float2 B = *(const float2*)(yrow + q*2 + 8);
    float4 u;
    u.x = A.x*a[0]; u.y = A.y*a[1]; u.z = B.x*a[2]; u.w = B.y*a[3];
    float4 un;
    un.x = u.x - cv[0]; un.y = u.y - cv[1]; un.z = u.z - cv[2]; un.w = u.w - cv[3];
    ((float4*)g_u)[i]  = u;
    ((float4*)g_un)[i] = un;
}

// ============================================================================
// Main pass via mma.sync bf16 (split-bf16, 3 terms), operand-swapped,
// with cp.async.cg double-buffered THREAD-LOCAL gather staging.
#define EDGE_STAGE_BYTES (12*512)              // 6 KB per stage
#define EDGE_WARP_BYTES  (2*EDGE_STAGE_BYTES)  // 12 KB per warp
#define EDGE_SMEM (4*EDGE_WARP_BYTES + 512)    // 49664 B

__device__ __forceinline__ void stage_point(uint32_t dlane, int qoff,
                                            int p, int j0, int j1) {
    int base = p & ~(NN-1);
    const char* cen = (const char*)g_un + (((size_t)p) << 8) + qoff;
    const char* r0  = (const char*)g_u  + (((size_t)(base + j0)) << 8) + qoff;
    const char* r1  = (const char*)g_u  + (((size_t)(base + j1)) << 8) + qoff;
    #pragma unroll
    for (int ks = 0; ks < 4; ks++) {
        CP16(dlane + (ks*3+0)*512, cen + ks*64);
        CP16(dlane + (ks*3+1)*512, r0  + ks*64);
        CP16(dlane + (ks*3+2)*512, r1  + ks*64);
    }
    CP_COMMIT();
}

__global__ void __launch_bounds__(128, 4) k_edge(const int* __restrict__ idx,
                                                 const float* __restrict__ W2) {
    extern __shared__ char esm[];
    float* sm_s = (float*)(esm + 4*EDGE_WARP_BYTES);
    float* sm_q = sm_s + 64;
    int t = threadIdx.x;
    int lane = t & 31, w = t >> 5;
    int g = lane >> 2, q = lane & 3;

    if (t < 64) { sm_s[t] = 0.f; sm_q[t] = 0.f; }

    // A = W2 fragments for this warp's 2 m-tiles (32 output channels), resident
    int mtb = (w & 1) * 2;
    uint32_t Ahi[2][4][4], Alo[2][4][4];
    #pragma unroll
    for (int mi = 0; mi < 2; mi++) {
        int o0 = (mtb + mi)*16 + g;
        #pragma unroll
        for (int ks = 0; ks < 4; ks++) {
            int cb = ks*16 + q*2;
            const float* r0 = W2 + o0*64 + cb;
            const float* r1 = W2 + (o0+8)*64 + cb;
            float2 a00 = *(const float2*)(r0);
            float2 a01 = *(const float2*)(r0 + 8);
            float2 a10 = *(const float2*)(r1);
            float2 a11 = *(const float2*)(r1 + 8);
            split2(a00.x, a00.y, Ahi[mi][ks][0], Alo[mi][ks][0]);
            split2(a10.x, a10.y, Ahi[mi][ks][1], Alo[mi][ks][1]);
            split2(a01.x, a01.y, Ahi[mi][ks][2], Alo[mi][ks][2]);
            split2(a11.x, a11.y, Ahi[mi][ks][3], Alo[mi][ks][3]);
        }
    }

    uint32_t dlane = smem_u32(esm) + w*EDGE_WARP_BYTES + lane*16;
    int qoff = q*16;
    int pslot = w >> 1;
    int pbase = blockIdx.x * 16 + pslot * 8;

    float sums[4], sumq[4];
    #pragma unroll
    for (int i = 0; i < 4; i++) { sums[i] = 0.f; sumq[i] = 0.f; }

    // prologue: stage point 0, prefetch idx for point 1
    int j0c = idx[pbase*KK + g],       j1c = idx[pbase*KK + 8 + g];
    int j0n = idx[(pbase+1)*KK + g],   j1n = idx[(pbase+1)*KK + 8 + g];
    stage_point(dlane, qoff, pbase, j0c, j1c);

    __syncthreads();   // sm_s/sm_q init visible before end-of-kernel atomics

    #pragma unroll 1
    for (int pi = 0; pi < 8; pi++) {
        int p = pbase + pi;
        uint32_t buf = dlane + (pi & 1) * EDGE_STAGE_BYTES;
        CP_WAIT0();                          // buf(pi) ready (staged last iter)

        // prefetch idx for pi+2 (clamped; covered by this point's MMA latency)
        int pn2 = pbase + ((pi + 2 < 8) ? pi + 2 : 7);
        int j0f = idx[pn2*KK + g], j1f = idx[pn2*KK + 8 + g];
        // stage pi+1 into the other buffer; flies during MMA+epilogue below
        if (pi < 7)
            stage_point(dlane + ((pi+1) & 1) * EDGE_STAGE_BYTES, qoff, p + 1, j0n, j1n);

        float D[2][2][4];
        #pragma unroll
        for (int mi = 0; mi < 2; mi++)
            #pragma unroll
            for (int nt = 0; nt < 2; nt++)
                #pragma unroll
                for (int i = 0; i < 4; i++) D[mi][nt][i] = 0.f;

        #pragma unroll
        for (int ks = 0; ks < 4; ks++) {
            float4 nf = lds128(buf + (ks*3+0)*512);
            float4 x0 = lds128(buf + (ks*3+1)*512);
            float4 x1 = lds128(buf + (ks*3+2)*512);
            uint32_t bh00, bl00, bh01, bl01;
            uint32_t bh10, bl10, bh11, bl11;
            split2(fmaxf(x0.x - nf.x, 0.f), fmaxf(x0.y - nf.y, 0.f), bh00, bl00);
            split2(fmaxf(x0.z - nf.z, 0.f), fmaxf(x0.w - nf.w, 0.f), bh01, bl01);
            split2(fmaxf(x1.x - nf.x, 0.f), fmaxf(x1.y - nf.y, 0.f), bh10, bl10);
            split2(fmaxf(x1.z - nf.z, 0.f), fmaxf(x1.w - nf.w, 0.f), bh11, bl11);
            #pragma unroll
            for (int mi = 0; mi < 2; mi++) {
                mma16816(D[mi][0], Ahi[mi][ks], bh00, bh01);
                mma16816(D[mi][0], Alo[mi][ks], bh00, bh01);
                mma16816(D[mi][0], Ahi[mi][ks], bl00, bl01);
                mma16816(D[mi][1], Ahi[mi][ks], bh10, bh11);
                mma16816(D[mi][1], Alo[mi][ks], bh10, bh11);
                mma16816(D[mi][1], Ahi[mi][ks], bl10, bl11);
            }
        }

        // reduce over neighbors: in-thread, then shfl over q
        #pragma unroll
        for (int mi = 0; mi < 2; mi++) {
            float d00 = D[mi][0][0], d01 = D[mi][0][1];
            float d10 = D[mi][1][0], d11 = D[mi][1][1];
            float e00 = D[mi][0][2], e01 = D[mi][0][3];
            float e10 = D[mi][1][2], e11 = D[mi][1][3];
            sums[mi*2]   += (d00 + d01) + (d10 + d11);
            sums[mi*2+1] += (e00 + e01) + (e10 + e11);
            sumq[mi*2]   = fmaf(d00,d00, fmaf(d01,d01, fmaf(d10,d10, fmaf(d11,d11, sumq[mi*2]))));
            sumq[mi*2+1] = fmaf(e00,e00, fmaf(e01,e01, fmaf(e10,e10, fmaf(e11,e11, sumq[mi*2+1]))));
            float mx0 = fmaxf(fmaxf(d00, d01), fmaxf(d10, d11));
            float mn0 = fminf(fminf(d00, d01), fminf(d10, d11));
            float mx1 = fmaxf(fmaxf(e00, e01), fmaxf(e10, e11));
            float mn1 = fminf(fminf(e00, e01), fminf(e10, e11));
            #pragma unroll
            for (int off = 1; off < 4; off <<= 1) {
                mx0 = fmaxf(mx0, __shfl_xor_sync(0xffffffffu, mx0, off));
                mn0 = fminf(mn0, __shfl_xor_sync(0xffffffffu, mn0, off));
                mx1 = fmaxf(mx1, __shfl_xor_sync(0xffffffffu, mx1, off));
                mn1 = fminf(mn1, __shfl_xor_sync(0xffffffffu, mn1, off));
            }
            if (q == 0) {
                int ch = (mtb + mi)*16 + g;
                g_zmax[(size_t)p*EE + ch]     = mx0;
                g_zmax[(size_t)p*EE + ch + 8] = mx1;
                g_zmin[(size_t)p*EE + ch]     = mn0;
                g_zmin[(size_t)p*EE + ch + 8] = mn1;
            }
        }
        j0n = j0f; j1n = j1f;
    }

    // BN2 sums: shfl-reduce over q, stage in smem, one global atomic per channel
    #pragma unroll
    for (int i = 0; i < 4; i++) {
        float s = sums[i], qq = sumq[i];
        #pragma unroll
        for (int off = 1; off < 4; off <<= 1) {
            s  += __shfl_xor_sync(0xffffffffu, s, off);
            qq += __shfl_xor_sync(0xffffffffu, qq, off);
        }
        if (q == 0) {
            int ch = (mtb + (i >> 1))*16 + g + (i & 1)*8;
            atomicAdd(&sm_s[ch], s);
            atomicAdd(&sm_q[ch], qq);
        }
    }
    __syncthreads();
    if (t < 64) {
        atomicAdd(&g_sum2[t],   sm_s[t]);
        atomicAdd(&g_sumsq2[t], sm_q[t]);
    }
}

// ============================================================================
// pooled m = relu(a2*z_sel+c2); z3 = W3@m -> out; BN3 partials -> 32 buckets.
// ms fill is now a COALESCED float4 sweep over the contiguous [64pt x 64ch]
// block (reads zmax+zmin, selects by sign of a2 from smem).
__global__ void k_pool3(const float* __restrict__ W3,
                        const float* __restrict__ g2,
                        const float* __restrict__ be2,
                        float* __restrict__ out) {
    __shared__ float ms[64][65];
    __shared__ float W3sT[CC][EE];
    __shared__ float a2s[64], c2s[64];
    int b = blockIdx.y;
    int n0 = blockIdx.x * 64;
    int t = threadIdx.x;
    for (int i = t; i < CC*EE; i += 256) {
        int o = i >> 6, c = i & 63;
        W3sT[c][o] = W3[i];
    }
    if (t < 64) {
        float m2 = g_sum2[t] * (1.f/CNT1);
        float v2 = fmaxf(g_sumsq2[t] * (1.f/CNT1) - m2*m2, 0.f);
        float a2o = g2[t] * rsqrtf(v2 + EPSV);
        a2s[t] = a2o;
        c2s[t] = be2[t] - a2o * m2;
    }
    __syncthreads();
    {
        const float4* zmx4 = (const float4*)(g_zmax + (size_t)(b*NN + n0)*EE);
        const float4* zmn4 = (const float4*)(g_zmin + (size_t)(b*NN + n0)*EE);
        #pragma unroll
        for (int i4 = t; i4 < 1024; i4 += 256) {
            int nl = i4 >> 4;
            int o0 = (i4 & 15) * 4;
            float4 zx = zmx4[i4];
            float4 zn = zmn4[i4];
            float a0 = a2s[o0],   c0 = c2s[o0];
            float a1 = a2s[o0+1], c1 = c2s[o0+1];
            float a2 = a2s[o0+2], c2 = c2s[o0+2];
            float a3 = a2s[o0+3], c3 = c2s[o0+3];
            ms[nl][o0]   = fmaxf(fmaf(a0, (a0 >= 0.f) ? zx.x : zn.x, c0), 0.f);
            ms[nl][o0+1] = fmaxf(fmaf(a1, (a1 >= 0.f) ? zx.y : zn.y, c1), 0.f);
            ms[nl][o0+2] = fmaxf(fmaf(a2, (a2 >= 0.f) ? zx.z : zn.z, c2), 0.f);
            ms[nl][o0+3] = fmaxf(fmaf(a3, (a3 >= 0.f) ? zx.w : zn.w, c3), 0.f);
        }
    }
    __syncthreads();
    int nl = t & 63;
    int ob = (t >> 6) * 16;
    float acc[16];
    #pragma unroll
    for (int i = 0; i < 16; i++) acc[i] = 0.f;
    #pragma unroll 4
    for (int c = 0; c < CC; c++) {
        float mv = ms[nl][c];
        #pragma unroll
        for (int i = 0; i < 16; i++)
            acc[i] = fmaf(W3sT[c][ob+i], mv, acc[i]);
    }
    #pragma unroll
    for (int i = 0; i < 16; i++)
        out[(b*EE + ob + i)*NN + n0 + nl] = acc[i];

    // BN3 partials: shfl-reduce over the 32 points in this warp, bucketed atomics
    int bucket = (blockIdx.y * 64 + blockIdx.x) & 31;
    #pragma unroll
    for (int i = 0; i < 16; i++) {
        float s = acc[i];
        float qv = acc[i] * acc[i];
        #pragma unroll
        for (int off = 16; off > 0; off >>= 1) {
            s  += __shfl_xor_sync(0xffffffffu, s, off);
            qv += __shfl_xor_sync(0xffffffffu, qv, off);
        }
        if ((t & 31) == 0) {
            atomicAdd(&g_bs3[bucket][ob + i], s);
            atomicAdd(&g_bs3[bucket][64 + ob + i], qv);
        }
    }
}

// BN3 + ReLU in place (folds the 32 buckets first)
__global__ void k_out(const float* __restrict__ g3, const float* __restrict__ be3,
                      float* __restrict__ out) {
    __shared__ float sa[EE], sc[EE];
    int t = threadIdx.x;
    if (t < EE) {
        float s = 0.f, qv = 0.f;
        #pragma unroll
        for (int bk = 0; bk < 32; bk++) {
            s  += g_bs3[bk][t];
            qv += g_bs3[bk][64 + t];
        }
        float m3 = s * (1.f/CNT3);
        float v3 = fmaxf(qv * (1.f/CNT3) - m3*m3, 0.f);
        float a3 = g3[t] * rsqrtf(v3 + EPSV);
        sa[t] = a3;
        sc[t] = be3[t] - a3 * m3;
    }
    __syncthreads();
    int gi = blockIdx.x * blockDim.x + t;
    int o = (gi >> 10) & 63;
    float4* out4 = (float4*)out;
    float4 v = out4[gi];
    float a = sa[o], c = sc[o];
    v.x = fmaxf(fmaf(a, v.x, c), 0.f);
    v.y = fmaxf(fmaf(a, v.y, c), 0.f);
    v.z = fmaxf(fmaf(a, v.z, c), 0.f);
    v.w = fmaxf(fmaf(a, v.w, c), 0.f);
    out4[gi] = v;
}

extern "C" void kernel_launch(void* const* d_in, const int* in_sizes, int n_in,
                              void* d_out, int out_size) {
    const float* x   = (const float*)d_in[0];
    const int*   idx = (const int*)  d_in[1];
    const float* W1  = (const float*)d_in[2];
    const float* g1  = (const float*)d_in[4];
    const float* be1 = (const float*)d_in[5];
    const float* W2  = (const float*)d_in[6];
    const float* g2  = (const float*)d_in[8];
    const float* be2 = (const float*)d_in[9];
    const float* W3  = (const float*)d_in[10];
    const float* g3  = (const float*)d_in[12];
    const float* be3 = (const float*)d_in[13];
    float* out = (float*)d_out;

    cudaFuncSetAttribute(k_edge, cudaFuncAttributeMaxDynamicSharedMemorySize, EDGE_SMEM);

    k_y1    <<<dim3(64, 8), 256>>>(x, W1);
    k_stats1<<<512, 256>>>(idx);
    k_prep  <<<2048, 256>>>(g1, be1);
    k_edge  <<<2048, 128, EDGE_SMEM>>>(idx, W2);
    k_pool3 <<<dim3(64, 8), 256>>>(W3, g2, be2, out);
    k_out   <<<2048, 256>>>(g3, be3, out);
}

// round 13
// speedup vs baseline: 1.0530x; 1.0125x over previous
#include <cuda_runtime.h>
#include <cuda_bf16.h>
#include <cstdint>

#define BB 8
#define CC 64
#define NN 4096
#define KK 16
#define EE 64
#define NPOINTS (BB*NN)            // 32768
#define CNT1 524288.0f             // B*N*K
#define CNT3 32768.0f              // B*N
#define EPSV 1e-5f

// ---- scratch (device globals: allocation-free rule) ----
__device__ float g_y1t[NPOINTS*EE];       // 8 MB  raw y1 transposed [point][c]
__device__ float g_u[NPOINTS*EE];         // 8 MB  permuted u = a1*y
__device__ float g_un[NPOINTS*EE];        // 8 MB  permuted un' = u - c1
__device__ float g_zmax[NPOINTS*EE];      // 8 MB
__device__ float g_zmin[NPOINTS*EE];      // 8 MB
__device__ float g_sum1[EE], g_sumsq1[EE];
__device__ float g_sum2[EE], g_sumsq2[EE];
__device__ float g_bs3[32][128];          // BN3 bucketed partials

// pack two fp32 into bf16x2 (first arg -> low half)
__device__ __forceinline__ uint32_t pack_bf2(float lo_e, float hi_e) {
    uint32_t r;
    asm("cvt.rn.bf16x2.f32 %0, %1, %2;" : "=r"(r) : "f"(hi_e), "f"(lo_e));
    return r;
}

__device__ __forceinline__ void mma16816(float d[4], const uint32_t a[4], uint32_t b0, uint32_t b1) {
    asm volatile(
        "mma.sync.aligned.m16n8k16.row.col.f32.bf16.bf16.f32 "
        "{%0,%1,%2,%3}, {%4,%5,%6,%7}, {%8,%9}, {%0,%1,%2,%3};"
        : "+f"(d[0]), "+f"(d[1]), "+f"(d[2]), "+f"(d[3])
        : "r"(a[0]), "r"(a[1]), "r"(a[2]), "r"(a[3]), "r"(b0), "r"(b1));
}

// split a packed pair (x,y) into hi (bf16) and lo (residual bf16)
__device__ __forceinline__ void split2(float x, float y, uint32_t& hi, uint32_t& lo) {
    hi = pack_bf2(x, y);
    float e0 = __uint_as_float(hi << 16);
    float e1 = __uint_as_float(hi & 0xffff0000u);
    lo = pack_bf2(x - e0, y - e1);
}

__device__ __forceinline__ uint32_t smem_u32(const void* p) {
    uint32_t a;
    asm("{ .reg .u64 t; cvta.to.shared.u64 t, %1; cvt.u32.u64 %0, t; }" : "=r"(a) : "l"(p));
    return a;
}
__device__ __forceinline__ float4 lds128(uint32_t a) {
    float4 v;
    asm volatile("ld.shared.v4.f32 {%0,%1,%2,%3}, [%4];"
                 : "=f"(v.x), "=f"(v.y), "=f"(v.z), "=f"(v.w) : "r"(a));
    return v;
}
__device__ __forceinline__ uint4 lds128u(uint32_t a) {
    uint4 v;
    asm volatile("ld.shared.v4.u32 {%0,%1,%2,%3}, [%4];"
                 : "=r"(v.x), "=r"(v.y), "=r"(v.z), "=r"(v.w) : "r"(a));
    return v;
}
__device__ __forceinline__ void sts128u(uint32_t a, uint4 v) {
    asm volatile("st.shared.v4.u32 [%0], {%1,%2,%3,%4};"
                 :: "r"(a), "r"(v.x), "r"(v.y), "r"(v.z), "r"(v.w) : "memory");
}
#define CP16(d, s) asm volatile("cp.async.cg.shared.global [%0], [%1], 16;" :: "r"(d), "l"(s) : "memory")
#define CP_COMMIT() asm volatile("cp.async.commit_group;" ::: "memory")
#define CP_WAIT2()  asm volatile("cp.async.wait_group 2;" ::: "memory")

// ============================================================================
// y1t[b][n][e] = sum_c W1[e][c] * x[b][c][n];  block(0,0) zeroes accumulators
__global__ void k_y1(const float* __restrict__ x, const float* __restrict__ W1) {
    __shared__ float xs[CC][64];
    __shared__ float W1sT[CC][EE];
    int b = blockIdx.y;
    int n0 = blockIdx.x * 64;
    int t = threadIdx.x;
    if (blockIdx.x == 0 && blockIdx.y == 0) {
        if (t < EE) {
            g_sum1[t]=0.f; g_sumsq1[t]=0.f;
            g_sum2[t]=0.f; g_sumsq2[t]=0.f;
        }
        for (int i = t; i < 32*128; i += 256) ((float*)g_bs3)[i] = 0.f;
    }
    for (int i = t; i < CC*EE; i += 256) {
        int o = i >> 6, c = i & 63;
        W1sT[c][o] = W1[i];
    }
    for (int i = t; i < CC*64; i += 256) {
        int c = i >> 6, j = i & 63;
        xs[c][j] = x[(b*CC + c)*NN + n0 + j];
    }
    __syncthreads();
    int e = t & 63;
    int nb = (t >> 6) * 16;
    float acc[16];
    #pragma unroll
    for (int i = 0; i < 16; i++) acc[i] = 0.f;
    #pragma unroll 4
    for (int c = 0; c < CC; c++) {
        float w = W1sT[c][e];
        #pragma unroll
        for (int i = 0; i < 16; i++) acc[i] = fmaf(w, xs[c][nb+i], acc[i]);
    }
    #pragma unroll
    for (int i = 0; i < 16; i++)
        g_y1t[(b*NN + n0 + nb + i)*EE + e] = acc[i];
}

// BN1 stats over d = y_j - y_n (float4 gathers, idx shared via shfl)
__global__ void k_stats1(const int* __restrict__ idx) {
    __shared__ float4 red_s[16][16];
    __shared__ float4 red_q[16][16];
    int t = threadIdx.x;
    int c4 = t & 15, g = t >> 4;
    float4 s = make_float4(0.f,0.f,0.f,0.f);
    float4 q = make_float4(0.f,0.f,0.f,0.f);
    int p0 = blockIdx.x * 64;
    #pragma unroll 1
    for (int pl = 0; pl < 4; pl++) {
        int point = p0 + g*4 + pl;
        int brow = point & ~(NN-1);
        int jown = idx[point*KK + c4];
        float4 yn = *(const float4*)(g_y1t + (size_t)point*EE + c4*4);
        #pragma unroll
        for (int k = 0; k < KK; k++) {
            int j = __shfl_sync(0xffffffffu, jown, ((t & 31) & 16) | k, 32);
            float4 yj = *(const float4*)(g_y1t + (size_t)(brow + j)*EE + c4*4);
            float dx = yj.x - yn.x, dy = yj.y - yn.y, dz = yj.z - yn.z, dw = yj.w - yn.w;
            s.x += dx; s.y += dy; s.z += dz; s.w += dw;
            q.x = fmaf(dx, dx, q.x); q.y = fmaf(dy, dy, q.y);
            q.z = fmaf(dz, dz, q.z); q.w = fmaf(dw, dw, q.w);
        }
    }
    red_s[g][c4] = s;
    red_q[g][c4] = q;
    __syncthreads();
    if (t < 64) {
        float ss = 0.f, qq = 0.f;
        #pragma unroll
        for (int gg = 0; gg < 16; gg++) {
            ss += ((const float*)&red_s[gg][t >> 2])[t & 3];
            qq += ((const float*)&red_q[gg][t >> 2])[t & 3];
        }
        atomicAdd(&g_sum1[t], ss);
        atomicAdd(&g_sumsq1[t], qq);
    }
}

// fold BN1 into y with CHANNEL PERMUTATION
__global__ void k_prep(const float* __restrict__ g1, const float* __restrict__ be1) {
    int i = blockIdx.x * blockDim.x + threadIdx.x;
    int point = i >> 4;
    int blk = (i >> 2) & 3;
    int q = i & 3;
    int cb = blk*16 + q*2;
    int co[4] = {cb, cb+1, cb+8, cb+9};
    float a[4], cv[4];
    #pragma unroll
    for (int j = 0; j < 4; j++) {
        int c = co[j];
        float m1 = g_sum1[c] * (1.f/CNT1);
        float v1 = fmaxf(g_sumsq1[c] * (1.f/CNT1) - m1*m1, 0.f);
        a[j] = g1[c] * rsqrtf(v1 + EPSV);
        cv[j] = be1[c] - a[j] * m1;
    }
    const float* yrow = g_y1t + (size_t)point*EE + blk*16;
    float2 A = *(const float2*)(yrow + q*2);
    float2 B = *(const float2*)(yrow + q*2 + 8);
    float4 u;
    u.x = A.x*a[0]; u.y = A.y*a[1]; u.z = B.x*a[2]; u.w = B.y*a[3];
    float4 un;
    un.x = u.x - cv[0]; un.y = u.y - cv[1]; un.z = u.z - cv[2]; un.w = u.w - cv[3];
    ((float4*)g_u)[i]  = u;
    ((float4*)g_un)[i] = un;
}

// ============================================================================
// Main pass: 4 warps share one point stream (16 pts/CTA); warp w owns m-tile w
// and converts only k-step w (shared via smem). 4-stage cp.async ring.
#define ST_BYTES  4352                   // 256 cen + 8*512 neighbor chunks
#define CONVA_OFF (4*ST_BYTES)           // 17408
#define CONVB_OFF (CONVA_OFF + 2048)     // 19456
#define RED_OFF   (CONVA_OFF + 4096)     // 21504
#define EDGE_SMEM (RED_OFF + 512)        // 22016

__device__ __forceinline__ void stage_point(uint32_t sbuf, int p, int j0, int j1,
                                            int w, int g, int qoff, int lane) {
    int base = p & ~(NN-1);
    const char* cen = (const char*)g_un + (((size_t)p) << 8);
    const char* r0  = (const char*)g_u  + (((size_t)(base + j0)) << 8);
    const char* r1  = (const char*)g_u  + (((size_t)(base + j1)) << 8);
    int ko = w*64 + qoff;
    if (g == 0) CP16(sbuf + ko, cen + ko);                    // cen stored once
    CP16(sbuf + 256 + (w*2+0)*512 + lane*16, r0 + ko);
    CP16(sbuf + 256 + (w*2+1)*512 + lane*16, r1 + ko);
    CP_COMMIT();
}

__global__ void __launch_bounds__(128, 6) k_edge(const int* __restrict__ idx,
                                                 const float* __restrict__ W2) {
    extern __shared__ char esm[];
    uint32_t sb = smem_u32(esm);
    float* sm_s = (float*)(esm + RED_OFF);
    float* sm_q = sm_s + 64;
    int t = threadIdx.x;
    int lane = t & 31, w = t >> 5;
    int g = lane >> 2, q = lane & 3;
    int qoff = q * 16;

    if (t < 64) { sm_s[t] = 0.f; sm_q[t] = 0.f; }

    // A = W2 fragments for this warp's single m-tile (16 output channels)
    uint32_t Ahi[4][4], Alo[4][4];
    {
        int o0 = w*16 + g;
        #pragma unroll
        for (int ks = 0; ks < 4; ks++) {
            int cb = ks*16 + q*2;
            const float* r0 = W2 + o0*64 + cb;
            const float* r1 = W2 + (o0+8)*64 + cb;
            float2 a00 = *(const float2*)(r0);
            float2 a01 = *(const float2*)(r0 + 8);
            float2 a10 = *(const float2*)(r1);
            float2 a11 = *(const float2*)(r1 + 8);
            split2(a00.x, a00.y, Ahi[ks][0], Alo[ks][0]);
            split2(a10.x, a10.y, Ahi[ks][1], Alo[ks][1]);
            split2(a01.x, a01.y, Ahi[ks][2], Alo[ks][2]);
            split2(a11.x, a11.y, Ahi[ks][3], Alo[ks][3]);
        }
    }

    int pbase = blockIdx.x * 16;

    // prologue: stage p0, p1; prefetch idx for p2
    {
        int a0 = idx[(pbase+0)*KK + g], a1 = idx[(pbase+0)*KK + 8 + g];
        int b0 = idx[(pbase+1)*KK + g], b1 = idx[(pbase+1)*KK + 8 + g];
        stage_point(sb + 0*ST_BYTES, pbase+0, a0, a1, w, g, qoff, lane);
        stage_point(sb + 1*ST_BYTES, pbase+1, b0, b1, w, g, qoff, lane);
    }
    int j0n = idx[(pbase+2)*KK + g], j1n = idx[(pbase+2)*KK + 8 + g];
    __syncthreads();   // sm_s/sm_q init visible; prologue stages ordered

    float sums[2], sumq[2];
    sums[0]=0.f; sums[1]=0.f; sumq[0]=0.f; sumq[1]=0.f;

    #pragma unroll 1
    for (int pi = 0; pi < 16; pi++) {
        int p = pbase + pi;
        // stage pi+2 (lookahead 2) or empty commit to keep group count uniform
        if (pi + 2 < 16)
            stage_point(sb + ((pi+2)&3)*ST_BYTES, p + 2, j0n, j1n, w, g, qoff, lane);
        else
            CP_COMMIT();
        // prefetch idx for pi+3
        int pn3 = (pi + 3 < 16) ? p + 3 : pbase + 15;
        int j0f = idx[pn3*KK + g], j1f = idx[pn3*KK + 8 + g];

        CP_WAIT2();        // group pi complete
        __syncthreads();   // all warps' stages for pi visible

        uint32_t buf = sb + (pi & 3)*ST_BYTES;
        // convert own k-step (ks = w), publish fragments to smem
        {
            float4 nf = lds128(buf + w*64 + qoff);
            float4 x0 = lds128(buf + 256 + (w*2+0)*512 + lane*16);
            float4 x1 = lds128(buf + 256 + (w*2+1)*512 + lane*16);
            uint32_t bh00, bl00, bh01, bl01;
            uint32_t bh10, bl10, bh11, bl11;
            split2(fmaxf(x0.x - nf.x, 0.f), fmaxf(x0.y - nf.y, 0.f), bh00, bl00);
            split2(fmaxf(x0.z - nf.z, 0.f), fmaxf(x0.w - nf.w, 0.f), bh01, bl01);
            split2(fmaxf(x1.x - nf.x, 0.f), fmaxf(x1.y - nf.y, 0.f), bh10, bl10);
            split2(fmaxf(x1.z - nf.z, 0.f), fmaxf(x1.w - nf.w, 0.f), bh11, bl11);
            sts128u(sb + CONVA_OFF + w*512 + lane*16, make_uint4(bh00, bh01, bl00, bl01));
            sts128u(sb + CONVB_OFF + w*512 + lane*16, make_uint4(bh10, bh11, bl10, bl11));
        }
        __syncthreads();   // fragments visible to all warps

        float D[2][4];
        #pragma unroll
        for (int nt = 0; nt < 2; nt++)
            #pragma unroll
            for (int i = 0; i < 4; i++) D[nt][i] = 0.f;

        #pragma unroll
        for (int ks = 0; ks < 4; ks++) {
            uint4 fa = lds128u(sb + CONVA_OFF + ks*512 + lane*16);
            uint4 fb = lds128u(sb + CONVB_OFF + ks*512 + lane*16);
            mma16816(D[0], Ahi[ks], fa.x, fa.y);
            mma16816(D[0], Alo[ks], fa.x, fa.y);
            mma16816(D[0], Ahi[ks], fa.z, fa.w);
            mma16816(D[1], Ahi[ks], fb.x, fb.y);
            mma16816(D[1], Alo[ks], fb.x, fb.y);
            mma16816(D[1], Ahi[ks], fb.z, fb.w);
        }

        // reduce over neighbors: in-thread, then shfl over q
        {
            float d00 = D[0][0], d01 = D[0][1];   // row g, nt0
            float d10 = D[1][0], d11 = D[1][1];   // row g, nt1
            float e00 = D[0][2], e01 = D[0][3];   // row g+8, nt0
            float e10 = D[1][2], e11 = D[1][3];
            sums[0] += (d00 + d01) + (d10 + d11);
            sums[1] += (e00 + e01) + (e10 + e11);
            sumq[0] = fmaf(d00,d00, fmaf(d01,d01, fmaf(d10,d10, fmaf(d11,d11, sumq[0]))));
            sumq[1] = fmaf(e00,e00, fmaf(e01,e01, fmaf(e10,e10, fmaf(e11,e11, sumq[1]))));
            float mx0 = fmaxf(fmaxf(d00, d01), fmaxf(d10, d11));
            float mn0 = fminf(fminf(d00, d01), fminf(d10, d11));
            float mx1 = fmaxf(fmaxf(e00, e01), fmaxf(e10, e11));
            float mn1 = fminf(fminf(e00, e01), fminf(e10, e11));
            #pragma unroll
            for (int off = 1; off < 4; off <<= 1) {
                mx0 = fmaxf(mx0, __shfl_xor_sync(0xffffffffu, mx0, off));
                mn0 = fminf(mn0, __shfl_xor_sync(0xffffffffu, mn0, off));
                mx1 = fmaxf(mx1, __shfl_xor_sync(0xffffffffu, mx1, off));
                mn1 = fminf(mn1, __shfl_xor_sync(0xffffffffu, mn1, off));
            }
            if (q == 0) {
                int ch = w*16 + g;
                g_zmax[(size_t)p*EE + ch]     = mx0;
                g_zmax[(size_t)p*EE + ch + 8] = mx1;
                g_zmin[(size_t)p*EE + ch]     = mn0;
                g_zmin[(size_t)p*EE + ch + 8] = mn1;
            }
        }
        j0n = j0f; j1n = j1f;
    }

    // BN2 sums: shfl-reduce over q, stage in smem, one global atomic per channel
    #pragma unroll
    for (int i = 0; i < 2; i++) {
        float s = sums[i], qq = sumq[i];
        #pragma unroll
        for (int off = 1; off < 4; off <<= 1) {
            s  += __shfl_xor_sync(0xffffffffu, s, off);
            qq += __shfl_xor_sync(0xffffffffu, qq, off);
        }
        if (q == 0) {
            int ch = w*16 + g + i*8;
            atomicAdd(&sm_s[ch], s);
            atomicAdd(&sm_q[ch], qq);
        }
    }
    __syncthreads();
    if (t < 64) {
        atomicAdd(&g_sum2[t],   sm_s[t]);
        atomicAdd(&g_sumsq2[t], sm_q[t]);
    }
}

// ============================================================================
// pooled m = relu(a2*z_sel+c2); z3 = W3@m -> out; BN3 partials -> 32 buckets.
__global__ void k_pool3(const float* __restrict__ W3,
                        const float* __restrict__ g2,
                        const float* __restrict__ be2,
                        float* __restrict__ out) {
    __shared__ float ms[64][65];
    __shared__ float W3sT[CC][EE];
    __shared__ float a2s[64], c2s[64];
    int b = blockIdx.y;
    int n0 = blockIdx.x * 64;
    int t = threadIdx.x;
    for (int i = t; i < CC*EE; i += 256) {
        int o = i >> 6, c = i & 63;
        W3sT[c][o] = W3[i];
    }
    if (t < 64) {
        float m2 = g_sum2[t] * (1.f/CNT1);
        float v2 = fmaxf(g_sumsq2[t] * (1.f/CNT1) - m2*m2, 0.f);
        float a2o = g2[t] * rsqrtf(v2 + EPSV);
        a2s[t] = a2o;
        c2s[t] = be2[t] - a2o * m2;
    }
    __syncthreads();
    {
        const float4* zmx4 = (const float4*)(g_zmax + (size_t)(b*NN + n0)*EE);
        const float4* zmn4 = (const float4*)(g_zmin + (size_t)(b*NN + n0)*EE);
        #pragma unroll
        for (int i4 = t; i4 < 1024; i4 += 256) {
            int nl = i4 >> 4;
            int o0 = (i4 & 15) * 4;
            float4 zx = zmx4[i4];
            float4 zn = zmn4[i4];
            float a0 = a2s[o0],   c0 = c2s[o0];
            float a1 = a2s[o0+1], c1 = c2s[o0+1];
            float a2 = a2s[o0+2], c2 = c2s[o0+2];
            float a3 = a2s[o0+3], c3 = c2s[o0+3];
            ms[nl][o0]   = fmaxf(fmaf(a0, (a0 >= 0.f) ? zx.x : zn.x, c0), 0.f);
            ms[nl][o0+1] = fmaxf(fmaf(a1, (a1 >= 0.f) ? zx.y : zn.y, c1), 0.f);
            ms[nl][o0+2] = fmaxf(fmaf(a2, (a2 >= 0.f) ? zx.z : zn.z, c2), 0.f);
            ms[nl][o0+3] = fmaxf(fmaf(a3, (a3 >= 0.f) ? zx.w : zn.w, c3), 0.f);
        }
    }
    __syncthreads();
    int nl = t & 63;
    int ob = (t >> 6) * 16;
    float acc[16];
    #pragma unroll
    for (int i = 0; i < 16; i++) acc[i] = 0.f;
    #pragma unroll 4
    for (int c = 0; c < CC; c++) {
        float mv = ms[nl][c];
        #pragma unroll
        for (int i = 0; i < 16; i++)
            acc[i] = fmaf(W3sT[c][ob+i], mv, acc[i]);
    }
    #pragma unroll
    for (int i = 0; i < 16; i++)
        out[(b*EE + ob + i)*NN + n0 + nl] = acc[i];

    int bucket = (blockIdx.y * 64 + blockIdx.x) & 31;
    #pragma unroll
    for (int i = 0; i < 16; i++) {
        float s = acc[i];
        float qv = acc[i] * acc[i];
        #pragma unroll
        for (int off = 16; off > 0; off >>= 1) {
            s  += __shfl_xor_sync(0xffffffffu, s, off);
            qv += __shfl_xor_sync(0xffffffffu, qv, off);
        }
        if ((t & 31) == 0) {
            atomicAdd(&g_bs3[bucket][ob + i], s);
            atomicAdd(&g_bs3[bucket][64 + ob + i], qv);
        }
    }
}

// BN3 + ReLU in place (folds the 32 buckets first)
__global__ void k_out(const float* __restrict__ g3, const float* __restrict__ be3,
                      float* __restrict__ out) {
    __shared__ float sa[EE], sc[EE];
    int t = threadIdx.x;
    if (t < EE) {
        float s = 0.f, qv = 0.f;
        #pragma unroll
        for (int bk = 0; bk < 32; bk++) {
            s  += g_bs3[bk][t];
            qv += g_bs3[bk][64 + t];
        }
        float m3 = s * (1.f/CNT3);
        float v3 = fmaxf(qv * (1.f/CNT3) - m3*m3, 0.f);
        float a3 = g3[t] * rsqrtf(v3 + EPSV);
        sa[t] = a3;
        sc[t] = be3[t] - a3 * m3;
    }
    __syncthreads();
    int gi = blockIdx.x * blockDim.x + t;
    int o = (gi >> 10) & 63;
    float4* out4 = (float4*)out;
    float4 v = out4[gi];
    float a = sa[o], c = sc[o];
    v.x = fmaxf(fmaf(a, v.x, c), 0.f);
    v.y = fmaxf(fmaf(a, v.y, c), 0.f);
    v.z = fmaxf(fmaf(a, v.z, c), 0.f);
    v.w = fmaxf(fmaf(a, v.w, c), 0.f);
    out4[gi] = v;
}

extern "C" void kernel_launch(void* const* d_in, const int* in_sizes, int n_in,
                              void* d_out, int out_size) {
    const float* x   = (const float*)d_in[0];
    const int*   idx = (const int*)  d_in[1];
    const float* W1  = (const float*)d_in[2];
    const float* g1  = (const float*)d_in[4];
    const float* be1 = (const float*)d_in[5];
    const float* W2  = (const float*)d_in[6];
    const float* g2  = (const float*)d_in[8];
    const float* be2 = (const float*)d_in[9];
    const float* W3  = (const float*)d_in[10];
    const float* g3  = (const float*)d_in[12];
    const float* be3 = (const float*)d_in[13];
    float* out = (float*)d_out;

    cudaFuncSetAttribute(k_edge, cudaFuncAttributeMaxDynamicSharedMemorySize, EDGE_SMEM);

    k_y1    <<<dim3(64, 8), 256>>>(x, W1);
    k_stats1<<<512, 256>>>(idx);
    k_prep  <<<2048, 256>>>(g1, be1);
    k_edge  <<<2048, 128, EDGE_SMEM>>>(idx, W2);
    k_pool3 <<<dim3(64, 8), 256>>>(W3, g2, be2, out);
    k_out   <<<2048, 256>>>(g3, be3, out);
}

// round 14
// speedup vs baseline: 1.1057x; 1.0500x over previous
#include <cuda_runtime.h>
#include <cuda_bf16.h>
#include <cstdint>

#define BB 8
#define CC 64
#define NN 4096
#define KK 16
#define EE 64
#define NPOINTS (BB*NN)            // 32768
#define CNT1 524288.0f             // B*N*K
#define CNT3 32768.0f              // B*N
#define EPSV 1e-5f

// ---- scratch (device globals: allocation-free rule) ----
// g_y1t holds y1 in PERMUTED channel layout: phys float4 slot (blk, q) holds
// orig channels {blk*16+2q, +1, blk*16+2q+8, +9}
__device__ float g_y1t[NPOINTS*EE];       // 8 MB
__device__ float g_zmax[NPOINTS*EE];      // 8 MB
__device__ float g_zmin[NPOINTS*EE];      // 8 MB
__device__ float g_sum1[EE], g_sumsq1[EE];   // PHYS channel order
__device__ float g_sum2[EE], g_sumsq2[EE];
__device__ float g_bs3[32][128];          // BN3 bucketed partials

// pack two fp32 into bf16x2 (first arg -> low half)
__device__ __forceinline__ uint32_t pack_bf2(float lo_e, float hi_e) {
    uint32_t r;
    asm("cvt.rn.bf16x2.f32 %0, %1, %2;" : "=r"(r) : "f"(hi_e), "f"(lo_e));
    return r;
}

__device__ __forceinline__ void mma16816(float d[4], const uint32_t a[4], uint32_t b0, uint32_t b1) {
    asm volatile(
        "mma.sync.aligned.m16n8k16.row.col.f32.bf16.bf16.f32 "
        "{%0,%1,%2,%3}, {%4,%5,%6,%7}, {%8,%9}, {%0,%1,%2,%3};"
        : "+f"(d[0]), "+f"(d[1]), "+f"(d[2]), "+f"(d[3])
        : "r"(a[0]), "r"(a[1]), "r"(a[2]), "r"(a[3]), "r"(b0), "r"(b1));
}

// split a packed pair (x,y) into hi (bf16) and lo (residual bf16)
__device__ __forceinline__ void split2(float x, float y, uint32_t& hi, uint32_t& lo) {
    hi = pack_bf2(x, y);
    float e0 = __uint_as_float(hi << 16);
    float e1 = __uint_as_float(hi & 0xffff0000u);
    lo = pack_bf2(x - e0, y - e1);
}

__device__ __forceinline__ uint32_t smem_u32(const void* p) {
    uint32_t a;
    asm("{ .reg .u64 t; cvta.to.shared.u64 t, %1; cvt.u32.u64 %0, t; }" : "=r"(a) : "l"(p));
    return a;
}
__device__ __forceinline__ float4 lds128(uint32_t a) {
    float4 v;
    asm volatile("ld.shared.v4.f32 {%0,%1,%2,%3}, [%4];"
                 : "=f"(v.x), "=f"(v.y), "=f"(v.z), "=f"(v.w) : "r"(a));
    return v;
}
__device__ __forceinline__ uint4 lds128u(uint32_t a) {
    uint4 v;
    asm volatile("ld.shared.v4.u32 {%0,%1,%2,%3}, [%4];"
                 : "=r"(v.x), "=r"(v.y), "=r"(v.z), "=r"(v.w) : "r"(a));
    return v;
}
__device__ __forceinline__ void sts128u(uint32_t a, uint4 v) {
    asm volatile("st.shared.v4.u32 [%0], {%1,%2,%3,%4};"
                 :: "r"(a), "r"(v.x), "r"(v.y), "r"(v.z), "r"(v.w) : "memory");
}
#define CP16(d, s) asm volatile("cp.async.cg.shared.global [%0], [%1], 16;" :: "r"(d), "l"(s) : "memory")
#define CP_COMMIT() asm volatile("cp.async.commit_group;" ::: "memory")
#define CP_WAIT2()  asm volatile("cp.async.wait_group 2;" ::: "memory")

// ============================================================================
// y1t[point][perm(e)] = sum_c W1[e][c] * x[b][c][n]; block(0,0) zeroes accums
__global__ void k_y1(const float* __restrict__ x, const float* __restrict__ W1) {
    __shared__ float xs[CC][64];
    __shared__ float W1sT[CC][EE];
    int b = blockIdx.y;
    int n0 = blockIdx.x * 64;
    int t = threadIdx.x;
    if (blockIdx.x == 0 && blockIdx.y == 0) {
        if (t < EE) {
            g_sum1[t]=0.f; g_sumsq1[t]=0.f;
            g_sum2[t]=0.f; g_sumsq2[t]=0.f;
        }
        for (int i = t; i < 32*128; i += 256) ((float*)g_bs3)[i] = 0.f;
    }
    for (int i = t; i < CC*EE; i += 256) {
        int o = i >> 6, c = i & 63;
        W1sT[c][o] = W1[i];
    }
    for (int i = t; i < CC*64; i += 256) {
        int c = i >> 6, j = i & 63;
        xs[c][j] = x[(b*CC + c)*NN + n0 + j];
    }
    __syncthreads();
    int e = t & 63;
    int nb = (t >> 6) * 16;
    // permuted store channel
    int r = e & 15, blkc = e >> 4;
    int pj = (r < 8) ? ((r >> 1)*4 + (r & 1)) : (((r-8) >> 1)*4 + 2 + (r & 1));
    int pe = blkc*16 + pj;
    float acc[16];
    #pragma unroll
    for (int i = 0; i < 16; i++) acc[i] = 0.f;
    #pragma unroll 4
    for (int c = 0; c < CC; c++) {
        float w = W1sT[c][e];
        #pragma unroll
        for (int i = 0; i < 16; i++) acc[i] = fmaf(w, xs[c][nb+i], acc[i]);
    }
    #pragma unroll
    for (int i = 0; i < 16; i++)
        g_y1t[(b*NN + n0 + nb + i)*EE + pe] = acc[i];
}

// BN1 stats over d = y_j - y_n (permuted data -> sums in PHYS order)
__global__ void k_stats1(const int* __restrict__ idx) {
    __shared__ float4 red_s[16][16];
    __shared__ float4 red_q[16][16];
    int t = threadIdx.x;
    int c4 = t & 15, g = t >> 4;
    float4 s = make_float4(0.f,0.f,0.f,0.f);
    float4 q = make_float4(0.f,0.f,0.f,0.f);
    int p0 = blockIdx.x * 64;
    #pragma unroll 1
    for (int pl = 0; pl < 4; pl++) {
        int point = p0 + g*4 + pl;
        int brow = point & ~(NN-1);
        int jown = idx[point*KK + c4];
        float4 yn = *(const float4*)(g_y1t + (size_t)point*EE + c4*4);
        #pragma unroll
        for (int k = 0; k < KK; k++) {
            int j = __shfl_sync(0xffffffffu, jown, ((t & 31) & 16) | k, 32);
            float4 yj = *(const float4*)(g_y1t + (size_t)(brow + j)*EE + c4*4);
            float dx = yj.x - yn.x, dy = yj.y - yn.y, dz = yj.z - yn.z, dw = yj.w - yn.w;
            s.x += dx; s.y += dy; s.z += dz; s.w += dw;
            q.x = fmaf(dx, dx, q.x); q.y = fmaf(dy, dy, q.y);
            q.z = fmaf(dz, dz, q.z); q.w = fmaf(dw, dw, q.w);
        }
    }
    red_s[g][c4] = s;
    red_q[g][c4] = q;
    __syncthreads();
    if (t < 64) {
        float ss = 0.f, qq = 0.f;
        #pragma unroll
        for (int gg = 0; gg < 16; gg++) {
            ss += ((const float*)&red_s[gg][t >> 2])[t & 3];
            qq += ((const float*)&red_q[gg][t >> 2])[t & 3];
        }
        atomicAdd(&g_sum1[t], ss);
        atomicAdd(&g_sumsq1[t], qq);
    }
}

// ============================================================================
// Main pass: 4 warps share one point stream (16 pts/CTA); warp w owns m-tile w
// and converts only k-step w (shared via smem). 4-stage cp.async ring.
// BN1 fold applied inline in the convert (a1/c1 register-resident).
#define ST_BYTES  4352                   // 256 cen + 8*512 neighbor chunks
#define CONVA_OFF (4*ST_BYTES)           // 17408
#define CONVB_OFF (CONVA_OFF + 2048)     // 19456
#define RED_OFF   (CONVA_OFF + 4096)     // 21504
#define EDGE_SMEM (RED_OFF + 512)        // 22016

__device__ __forceinline__ void stage_point(uint32_t sbuf, int p, int j0, int j1,
                                            int w, int g, int qoff, int lane) {
    int base = p & ~(NN-1);
    const char* cen = (const char*)g_y1t + (((size_t)p) << 8);
    const char* r0  = (const char*)g_y1t + (((size_t)(base + j0)) << 8);
    const char* r1  = (const char*)g_y1t + (((size_t)(base + j1)) << 8);
    int ko = w*64 + qoff;
    if (g == 0) CP16(sbuf + ko, cen + ko);                    // cen stored once
    CP16(sbuf + 256 + (w*2+0)*512 + lane*16, r0 + ko);
    CP16(sbuf + 256 + (w*2+1)*512 + lane*16, r1 + ko);
    CP_COMMIT();
}

__global__ void __launch_bounds__(128, 6) k_edge(const int* __restrict__ idx,
                                                 const float* __restrict__ W2,
                                                 const float* __restrict__ g1,
                                                 const float* __restrict__ be1) {
    extern __shared__ char esm[];
    uint32_t sb = smem_u32(esm);
    float* sm_s = (float*)(esm + RED_OFF);
    float* sm_q = sm_s + 64;
    int t = threadIdx.x;
    int lane = t & 31, w = t >> 5;
    int g = lane >> 2, q = lane & 3;
    int qoff = q * 16;

    if (t < 64) { sm_s[t] = 0.f; sm_q[t] = 0.f; }

    // BN1 fold for this thread's 4 phys channels (k-step w, float slice q*4)
    float a1v[4], c1v[4];
    #pragma unroll
    for (int j = 0; j < 4; j++) {
        int phys = w*16 + q*4 + j;
        int orig = w*16 + ((j < 2) ? (q*2 + j) : (q*2 + 8 + (j - 2)));
        float m1 = g_sum1[phys] * (1.f/CNT1);
        float v1 = fmaxf(g_sumsq1[phys] * (1.f/CNT1) - m1*m1, 0.f);
        a1v[j] = g1[orig] * rsqrtf(v1 + EPSV);
        c1v[j] = be1[orig] - a1v[j] * m1;
    }

    // A = W2 fragments for this warp's single m-tile (16 output channels)
    uint32_t Ahi[4][4], Alo[4][4];
    {
        int o0 = w*16 + g;
        #pragma unroll
        for (int ks = 0; ks < 4; ks++) {
            int cb = ks*16 + q*2;
            const float* r0 = W2 + o0*64 + cb;
            const float* r1 = W2 + (o0+8)*64 + cb;
            float2 a00 = *(const float2*)(r0);
            float2 a01 = *(const float2*)(r0 + 8);
            float2 a10 = *(const float2*)(r1);
            float2 a11 = *(const float2*)(r1 + 8);
            split2(a00.x, a00.y, Ahi[ks][0], Alo[ks][0]);
            split2(a10.x, a10.y, Ahi[ks][1], Alo[ks][1]);
            split2(a01.x, a01.y, Ahi[ks][2], Alo[ks][2]);
            split2(a11.x, a11.y, Ahi[ks][3], Alo[ks][3]);
        }
    }

    int pbase = blockIdx.x * 16;

    // prologue: stage p0, p1; prefetch idx for p2
    {
        int a0 = idx[(pbase+0)*KK + g], a1 = idx[(pbase+0)*KK + 8 + g];
        int b0 = idx[(pbase+1)*KK + g], b1 = idx[(pbase+1)*KK + 8 + g];
        stage_point(sb + 0*ST_BYTES, pbase+0, a0, a1, w, g, qoff, lane);
        stage_point(sb + 1*ST_BYTES, pbase+1, b0, b1, w, g, qoff, lane);
    }
    int j0n = idx[(pbase+2)*KK + g], j1n = idx[(pbase+2)*KK + 8 + g];
    __syncthreads();   // sm_s/sm_q init visible; prologue stages ordered

    float sums[2], sumq[2];
    sums[0]=0.f; sums[1]=0.f; sumq[0]=0.f; sumq[1]=0.f;

    #pragma unroll 1
    for (int pi = 0; pi < 16; pi++) {
        int p = pbase + pi;
        if (pi + 2 < 16)
            stage_point(sb + ((pi+2)&3)*ST_BYTES, p + 2, j0n, j1n, w, g, qoff, lane);
        else
            CP_COMMIT();
        int pn3 = (pi + 3 < 16) ? p + 3 : pbase + 15;
        int j0f = idx[pn3*KK + g], j1f = idx[pn3*KK + 8 + g];

        CP_WAIT2();        // group pi complete
        __syncthreads();   // all warps' stages for pi visible

        uint32_t buf = sb + (pi & 3)*ST_BYTES;
        // convert own k-step (ks = w) with inline BN1 fold, publish to smem
        {
            float4 nf = lds128(buf + w*64 + qoff);
            float4 x0 = lds128(buf + 256 + (w*2+0)*512 + lane*16);
            float4 x1 = lds128(buf + 256 + (w*2+1)*512 + lane*16);
            float h00 = fmaxf(fmaf(a1v[0], x0.x - nf.x, c1v[0]), 0.f);
            float h01 = fmaxf(fmaf(a1v[1], x0.y - nf.y, c1v[1]), 0.f);
            float h02 = fmaxf(fmaf(a1v[2], x0.z - nf.z, c1v[2]), 0.f);
            float h03 = fmaxf(fmaf(a1v[3], x0.w - nf.w, c1v[3]), 0.f);
            float h10 = fmaxf(fmaf(a1v[0], x1.x - nf.x, c1v[0]), 0.f);
            float h11 = fmaxf(fmaf(a1v[1], x1.y - nf.y, c1v[1]), 0.f);
            float h12 = fmaxf(fmaf(a1v[2], x1.z - nf.z, c1v[2]), 0.f);
            float h13 = fmaxf(fmaf(a1v[3], x1.w - nf.w, c1v[3]), 0.f);
            uint32_t bh00, bl00, bh01, bl01;
            uint32_t bh10, bl10, bh11, bl11;
            split2(h00, h01, bh00, bl00);
            split2(h02, h03, bh01, bl01);
            split2(h10, h11, bh10, bl10);
            split2(h12, h13, bh11, bl11);
            sts128u(sb + CONVA_OFF + w*512 + lane*16, make_uint4(bh00, bh01, bl00, bl01));
            sts128u(sb + CONVB_OFF + w*512 + lane*16, make_uint4(bh10, bh11, bl10, bl11));
        }
        __syncthreads();   // fragments visible to all warps

        float D[2][4];
        #pragma unroll
        for (int nt = 0; nt < 2; nt++)
            #pragma unroll
            for (int i = 0; i < 4; i++) D[nt][i] = 0.f;

        #pragma unroll
        for (int ks = 0; ks < 4; ks++) {
            uint4 fa = lds128u(sb + CONVA_OFF + ks*512 + lane*16);
            uint4 fb = lds128u(sb + CONVB_OFF + ks*512 + lane*16);
            mma16816(D[0], Ahi[ks], fa.x, fa.y);
            mma16816(D[0], Alo[ks], fa.x, fa.y);
            mma16816(D[0], Ahi[ks], fa.z, fa.w);
            mma16816(D[1], Ahi[ks], fb.x, fb.y);
            mma16816(D[1], Alo[ks], fb.x, fb.y);
            mma16816(D[1], Ahi[ks], fb.z, fb.w);
        }

        // reduce over neighbors: in-thread, then shfl over q
        {
            float d00 = D[0][0], d01 = D[0][1];
            float d10 = D[1][0], d11 = D[1][1];
            float e00 = D[0][2], e01 = D[0][3];
            float e10 = D[1][2], e11 = D[1][3];
            sums[0] += (d00 + d01) + (d10 + d11);
            sums[1] += (e00 + e01) + (e10 + e11);
            sumq[0] = fmaf(d00,d00, fmaf(d01,d01, fmaf(d10,d10, fmaf(d11,d11, sumq[0]))));
            sumq[1] = fmaf(e00,e00, fmaf(e01,e01, fmaf(e10,e10, fmaf(e11,e11, sumq[1]))));
            float mx0 = fmaxf(fmaxf(d00, d01), fmaxf(d10, d11));
            float mn0 = fminf(fminf(d00, d01), fminf(d10, d11));
            float mx1 = fmaxf(fmaxf(e00, e01), fmaxf(e10, e11));
            float mn1 = fminf(fminf(e00, e01), fminf(e10, e11));
            #pragma unroll
            for (int off = 1; off < 4; off <<= 1) {
                mx0 = fmaxf(mx0, __shfl_xor_sync(0xffffffffu, mx0, off));
                mn0 = fminf(mn0, __shfl_xor_sync(0xffffffffu, mn0, off));
                mx1 = fmaxf(mx1, __shfl_xor_sync(0xffffffffu, mx1, off));
                mn1 = fminf(mn1, __shfl_xor_sync(0xffffffffu, mn1, off));
            }
            if (q == 0) {
                int ch = w*16 + g;
                g_zmax[(size_t)p*EE + ch]     = mx0;
                g_zmax[(size_t)p*EE + ch + 8] = mx1;
                g_zmin[(size_t)p*EE + ch]     = mn0;
                g_zmin[(size_t)p*EE + ch + 8] = mn1;
            }
        }
        j0n = j0f; j1n = j1f;
    }

    // BN2 sums: shfl-reduce over q, stage in smem, one global atomic per channel
    #pragma unroll
    for (int i = 0; i < 2; i++) {
        float s = sums[i], qq = sumq[i];
        #pragma unroll
        for (int off = 1; off < 4; off <<= 1) {
            s  += __shfl_xor_sync(0xffffffffu, s, off);
            qq += __shfl_xor_sync(0xffffffffu, qq, off);
        }
        if (q == 0) {
            int ch = w*16 + g + i*8;
            atomicAdd(&sm_s[ch], s);
            atomicAdd(&sm_q[ch], qq);
        }
    }
    __syncthreads();
    if (t < 64) {
        atomicAdd(&g_sum2[t],   sm_s[t]);
        atomicAdd(&g_sumsq2[t], sm_q[t]);
    }
}

// ============================================================================
// pooled m = relu(a2*z_sel+c2); z3 = W3@m -> out; BN3 partials -> 32 buckets.
__global__ void k_pool3(const float* __restrict__ W3,
                        const float* __restrict__ g2,
                        const float* __restrict__ be2,
                        float* __restrict__ out) {
    __shared__ float ms[64][65];
    __shared__ float W3sT[CC][EE];
    __shared__ float a2s[64], c2s[64];
    int b = blockIdx.y;
    int n0 = blockIdx.x * 64;
    int t = threadIdx.x;
    for (int i = t; i < CC*EE; i += 256) {
        int o = i >> 6, c = i & 63;
        W3sT[c][o] = W3[i];
    }
    if (t < 64) {
        float m2 = g_sum2[t] * (1.f/CNT1);
        float v2 = fmaxf(g_sumsq2[t] * (1.f/CNT1) - m2*m2, 0.f);
        float a2o = g2[t] * rsqrtf(v2 + EPSV);
        a2s[t] = a2o;
        c2s[t] = be2[t] - a2o * m2;
    }
    __syncthreads();
    {
        const float4* zmx4 = (const float4*)(g_zmax + (size_t)(b*NN + n0)*EE);
        const float4* zmn4 = (const float4*)(g_zmin + (size_t)(b*NN + n0)*EE);
        #pragma unroll
        for (int i4 = t; i4 < 1024; i4 += 256) {
            int nl = i4 >> 4;
            int o0 = (i4 & 15) * 4;
            float4 zx = zmx4[i4];
            float4 zn = zmn4[i4];
            float a0 = a2s[o0],   c0 = c2s[o0];
            float a1 = a2s[o0+1], c1 = c2s[o0+1];
            float a2 = a2s[o0+2], c2 = c2s[o0+2];
            float a3 = a2s[o0+3], c3 = c2s[o0+3];
            ms[nl][o0]   = fmaxf(fmaf(a0, (a0 >= 0.f) ? zx.x : zn.x, c0), 0.f);
            ms[nl][o0+1] = fmaxf(fmaf(a1, (a1 >= 0.f) ? zx.y : zn.y, c1), 0.f);
            ms[nl][o0+2] = fmaxf(fmaf(a2, (a2 >= 0.f) ? zx.z : zn.z, c2), 0.f);
            ms[nl][o0+3] = fmaxf(fmaf(a3, (a3 >= 0.f) ? zx.w : zn.w, c3), 0.f);
        }
    }
    __syncthreads();
    int nl = t & 63;
    int ob = (t >> 6) * 16;
    float acc[16];
    #pragma unroll
    for (int i = 0; i < 16; i++) acc[i] = 0.f;
    #pragma unroll 4
    for (int c = 0; c < CC; c++) {
        float mv = ms[nl][c];
        #pragma unroll
        for (int i = 0; i < 16; i++)
            acc[i] = fmaf(W3sT[c][ob+i], mv, acc[i]);
    }
    #pragma unroll
    for (int i = 0; i < 16; i++)
        out[(b*EE + ob + i)*NN + n0 + nl] = acc[i];

    int bucket = (blockIdx.y * 64 + blockIdx.x) & 31;
    #pragma unroll
    for (int i = 0; i < 16; i++) {
        float s = acc[i];
        float qv = acc[i] * acc[i];
        #pragma unroll
        for (int off = 16; off > 0; off >>= 1) {
            s  += __shfl_xor_sync(0xffffffffu, s, off);
            qv += __shfl_xor_sync(0xffffffffu, qv, off);
        }
        if ((t & 31) == 0) {
            atomicAdd(&g_bs3[bucket][ob + i], s);
            atomicAdd(&g_bs3[bucket][64 + ob + i], qv);
        }
    }
}

// BN3 + ReLU in place (folds the 32 buckets first)
__global__ void k_out(const float* __restrict__ g3, const float* __restrict__ be3,
                      float* __restrict__ out) {
    __shared__ float sa[EE], sc[EE];
    int t = threadIdx.x;
    if (t < EE) {
        float s = 0.f, qv = 0.f;
        #pragma unroll
        for (int bk = 0; bk < 32; bk++) {
            s  += g_bs3[bk][t];
            qv += g_bs3[bk][64 + t];
        }
        float m3 = s * (1.f/CNT3);
        float v3 = fmaxf(qv * (1.f/CNT3) - m3*m3, 0.f);
        float a3 = g3[t] * rsqrtf(v3 + EPSV);
        sa[t] = a3;
        sc[t] = be3[t] - a3 * m3;
    }
    __syncthreads();
    int gi = blockIdx.x * blockDim.x + t;
    int o = (gi >> 10) & 63;
    float4* out4 = (float4*)out;
    float4 v = out4[gi];
    float a = sa[o], c = sc[o];
    v.x = fmaxf(fmaf(a, v.x, c), 0.f);
    v.y = fmaxf(fmaf(a, v.y, c), 0.f);
    v.z = fmaxf(fmaf(a, v.z, c), 0.f);
    v.w = fmaxf(fmaf(a, v.w, c), 0.f);
    out4[gi] = v;
}

extern "C" void kernel_launch(void* const* d_in, const int* in_sizes, int n_in,
                              void* d_out, int out_size) {
    const float* x   = (const float*)d_in[0];
    const int*   idx = (const int*)  d_in[1];
    const float* W1  = (const float*)d_in[2];
    const float* g1  = (const float*)d_in[4];
    const float* be1 = (const float*)d_in[5];
    const float* W2  = (const float*)d_in[6];
    const float* g2  = (const float*)d_in[8];
    const float* be2 = (const float*)d_in[9];
    const float* W3  = (const float*)d_in[10];
    const float* g3  = (const float*)d_in[12];
    const float* be3 = (const float*)d_in[13];
    float* out = (float*)d_out;

    cudaFuncSetAttribute(k_edge, cudaFuncAttributeMaxDynamicSharedMemorySize, EDGE_SMEM);

    k_y1    <<<dim3(64, 8), 256>>>(x, W1);
    k_stats1<<<512, 256>>>(idx);
    k_edge  <<<2048, 128, EDGE_SMEM>>>(idx, W2, g1, be1);
    k_pool3 <<<dim3(64, 8), 256>>>(W3, g2, be2, out);
    k_out   <<<2048, 256>>>(g3, be3, out);
}

// round 15
// speedup vs baseline: 1.2790x; 1.1568x over previous
#include <cuda_runtime.h>
#include <cuda_bf16.h>
#include <cstdint>

#define BB 8
#define CC 64
#define NN 4096
#define KK 16
#define EE 64
#define NPOINTS (BB*NN)            // 32768
#define CNT1 524288.0f             // B*N*K
#define CNT3 32768.0f              // B*N
#define EPSV 1e-5f

// ---- scratch (device globals: allocation-free rule) ----
// g_y1t holds y1 in PERMUTED channel layout: phys float4 slot (blk, q) holds
// orig channels {blk*16+2q, +1, blk*16+2q+8, +9}
__device__ float g_y1t[NPOINTS*EE];       // 8 MB
__device__ float g_zmax[NPOINTS*EE];      // 8 MB
__device__ float g_zmin[NPOINTS*EE];      // 8 MB
__device__ float g_sum1[EE], g_sumsq1[EE];   // PHYS channel order
__device__ float g_sum2[EE], g_sumsq2[EE];
__device__ float g_bs3[32][128];          // BN3 bucketed partials

// pack two fp32 into bf16x2 (first arg -> low half)
__device__ __forceinline__ uint32_t pack_bf2(float lo_e, float hi_e) {
    uint32_t r;
    asm("cvt.rn.bf16x2.f32 %0, %1, %2;" : "=r"(r) : "f"(hi_e), "f"(lo_e));
    return r;
}

__device__ __forceinline__ void mma16816(float d[4], const uint32_t a[4], uint32_t b0, uint32_t b1) {
    asm volatile(
        "mma.sync.aligned.m16n8k16.row.col.f32.bf16.bf16.f32 "
        "{%0,%1,%2,%3}, {%4,%5,%6,%7}, {%8,%9}, {%0,%1,%2,%3};"
        : "+f"(d[0]), "+f"(d[1]), "+f"(d[2]), "+f"(d[3])
        : "r"(a[0]), "r"(a[1]), "r"(a[2]), "r"(a[3]), "r"(b0), "r"(b1));
}

// split a packed pair (x,y) into hi (bf16) and lo (residual bf16)
__device__ __forceinline__ void split2(float x, float y, uint32_t& hi, uint32_t& lo) {
    hi = pack_bf2(x, y);
    float e0 = __uint_as_float(hi << 16);
    float e1 = __uint_as_float(hi & 0xffff0000u);
    lo = pack_bf2(x - e0, y - e1);
}

__device__ __forceinline__ uint32_t smem_u32(const void* p) {
    uint32_t a;
    asm("{ .reg .u64 t; cvta.to.shared.u64 t, %1; cvt.u32.u64 %0, t; }" : "=r"(a) : "l"(p));
    return a;
}
__device__ __forceinline__ float4 lds128(uint32_t a) {
    float4 v;
    asm volatile("ld.shared.v4.f32 {%0,%1,%2,%3}, [%4];"
                 : "=f"(v.x), "=f"(v.y), "=f"(v.z), "=f"(v.w) : "r"(a));
    return v;
}
__device__ __forceinline__ uint4 lds128u(uint32_t a) {
    uint4 v;
    asm volatile("ld.shared.v4.u32 {%0,%1,%2,%3}, [%4];"
                 : "=r"(v.x), "=r"(v.y), "=r"(v.z), "=r"(v.w) : "r"(a));
    return v;
}
__device__ __forceinline__ void sts128u(uint32_t a, uint4 v) {
    asm volatile("st.shared.v4.u32 [%0], {%1,%2,%3,%4};"
                 :: "r"(a), "r"(v.x), "r"(v.y), "r"(v.z), "r"(v.w) : "memory");
}
#define CP16(d, s) asm volatile("cp.async.cg.shared.global [%0], [%1], 16;" :: "r"(d), "l"(s) : "memory")
#define CP_COMMIT() asm volatile("cp.async.commit_group;" ::: "memory")
#define CP_WAIT2()  asm volatile("cp.async.wait_group 2;" ::: "memory")

// ============================================================================
// y1t[point][perm(e)] = sum_c W1[e][c] * x[b][c][n]; block(0,0) zeroes accums
__global__ void k_y1(const float* __restrict__ x, const float* __restrict__ W1) {
    __shared__ float xs[CC][64];
    __shared__ float W1sT[CC][EE];
    int b = blockIdx.y;
    int n0 = blockIdx.x * 64;
    int t = threadIdx.x;
    if (blockIdx.x == 0 && blockIdx.y == 0) {
        if (t < EE) {
            g_sum1[t]=0.f; g_sumsq1[t]=0.f;
            g_sum2[t]=0.f; g_sumsq2[t]=0.f;
        }
        for (int i = t; i < 32*128; i += 256) ((float*)g_bs3)[i] = 0.f;
    }
    for (int i = t; i < CC*EE; i += 256) {
        int o = i >> 6, c = i & 63;
        W1sT[c][o] = W1[i];
    }
    for (int i = t; i < CC*64; i += 256) {
        int c = i >> 6, j = i & 63;
        xs[c][j] = x[(b*CC + c)*NN + n0 + j];
    }
    __syncthreads();
    int e = t & 63;
    int nb = (t >> 6) * 16;
    // permuted store channel
    int r = e & 15, blkc = e >> 4;
    int pj = (r < 8) ? ((r >> 1)*4 + (r & 1)) : (((r-8) >> 1)*4 + 2 + (r & 1));
    int pe = blkc*16 + pj;
    float acc[16];
    #pragma unroll
    for (int i = 0; i < 16; i++) acc[i] = 0.f;
    #pragma unroll 4
    for (int c = 0; c < CC; c++) {
        float w = W1sT[c][e];
        #pragma unroll
        for (int i = 0; i < 16; i++) acc[i] = fmaf(w, xs[c][nb+i], acc[i]);
    }
    #pragma unroll
    for (int i = 0; i < 16; i++)
        g_y1t[(b*NN + n0 + nb + i)*EE + pe] = acc[i];
}

// BN1 stats over d = y_j - y_n (permuted data -> sums in PHYS order)
__global__ void k_stats1(const int* __restrict__ idx) {
    __shared__ float4 red_s[16][16];
    __shared__ float4 red_q[16][16];
    int t = threadIdx.x;
    int c4 = t & 15, g = t >> 4;
    float4 s = make_float4(0.f,0.f,0.f,0.f);
    float4 q = make_float4(0.f,0.f,0.f,0.f);
    int p0 = blockIdx.x * 64;
    #pragma unroll 1
    for (int pl = 0; pl < 4; pl++) {
        int point = p0 + g*4 + pl;
        int brow = point & ~(NN-1);
        int jown = idx[point*KK + c4];
        float4 yn = *(const float4*)(g_y1t + (size_t)point*EE + c4*4);
        #pragma unroll
        for (int k = 0; k < KK; k++) {
            int j = __shfl_sync(0xffffffffu, jown, ((t & 31) & 16) | k, 32);
            float4 yj = *(const float4*)(g_y1t + (size_t)(brow + j)*EE + c4*4);
            float dx = yj.x - yn.x, dy = yj.y - yn.y, dz = yj.z - yn.z, dw = yj.w - yn.w;
            s.x += dx; s.y += dy; s.z += dz; s.w += dw;
            q.x = fmaf(dx, dx, q.x); q.y = fmaf(dy, dy, q.y);
            q.z = fmaf(dz, dz, q.z); q.w = fmaf(dw, dw, q.w);
        }
    }
    red_s[g][c4] = s;
    red_q[g][c4] = q;
    __syncthreads();
    if (t < 64) {
        float ss = 0.f, qq = 0.f;
        #pragma unroll
        for (int gg = 0; gg < 16; gg++) {
            ss += ((const float*)&red_s[gg][t >> 2])[t & 3];
            qq += ((const float*)&red_q[gg][t >> 2])[t & 3];
        }
        atomicAdd(&g_sum1[t], ss);
        atomicAdd(&g_sumsq1[t], qq);
    }
}

// ============================================================================
// Main pass: 4 warps share one point stream (16 pts/CTA); warp w owns m-tile w
// and converts only k-step w (shared via smem). 4-stage cp.async ring.
// BN1 fold applied inline in the convert (a1/c1 register-resident).
#define ST_BYTES  4352                   // 256 cen + 8*512 neighbor chunks
#define CONVA_OFF (4*ST_BYTES)           // 17408
#define CONVB_OFF (CONVA_OFF + 2048)     // 19456
#define RED_OFF   (CONVA_OFF + 4096)     // 21504
#define EDGE_SMEM (RED_OFF + 512)        // 22016

__device__ __forceinline__ void stage_point(uint32_t sbuf, int p, int j0, int j1,
                                            int w, int g, int qoff, int lane) {
    int base = p & ~(NN-1);
    const char* cen = (const char*)g_y1t + (((size_t)p) << 8);
    const char* r0  = (const char*)g_y1t + (((size_t)(base + j0)) << 8);
    const char* r1  = (const char*)g_y1t + (((size_t)(base + j1)) << 8);
    int ko = w*64 + qoff;
    if (g == 0) CP16(sbuf + ko, cen + ko);                    // cen stored once
    CP16(sbuf + 256 + (w*2+0)*512 + lane*16, r0 + ko);
    CP16(sbuf + 256 + (w*2+1)*512 + lane*16, r1 + ko);
    CP_COMMIT();
}

__global__ void __launch_bounds__(128, 6) k_edge(const int* __restrict__ idx,
                                                 const float* __restrict__ W2,
                                                 const float* __restrict__ g1,
                                                 const float* __restrict__ be1) {
    extern __shared__ char esm[];
    uint32_t sb = smem_u32(esm);
    float* sm_s = (float*)(esm + RED_OFF);
    float* sm_q = sm_s + 64;
    int t = threadIdx.x;
    int lane = t & 31, w = t >> 5;
    int g = lane >> 2, q = lane & 3;
    int qoff = q * 16;

    if (t < 64) { sm_s[t] = 0.f; sm_q[t] = 0.f; }

    // BN1 fold for this thread's 4 phys channels (k-step w, float slice q*4)
    float a1v[4], c1v[4];
    #pragma unroll
    for (int j = 0; j < 4; j++) {
        int phys = w*16 + q*4 + j;
        int orig = w*16 + ((j < 2) ? (q*2 + j) : (q*2 + 8 + (j - 2)));
        float m1 = g_sum1[phys] * (1.f/CNT1);
        float v1 = fmaxf(g_sumsq1[phys] * (1.f/CNT1) - m1*m1, 0.f);
        a1v[j] = g1[orig] * rsqrtf(v1 + EPSV);
        c1v[j] = be1[orig] - a1v[j] * m1;
    }

    // A = W2 fragments for this warp's single m-tile (16 output channels)
    uint32_t Ahi[4][4], Alo[4][4];
    {
        int o0 = w*16 + g;
        #pragma unroll
        for (int ks = 0; ks < 4; ks++) {
            int cb = ks*16 + q*2;
            const float* r0 = W2 + o0*64 + cb;
            const float* r1 = W2 + (o0+8)*64 + cb;
            float2 a00 = *(const float2*)(r0);
            float2 a01 = *(const float2*)(r0 + 8);
            float2 a10 = *(const float2*)(r1);
            float2 a11 = *(const float2*)(r1 + 8);
            split2(a00.x, a00.y, Ahi[ks][0], Alo[ks][0]);
            split2(a10.x, a10.y, Ahi[ks][1], Alo[ks][1]);
            split2(a01.x, a01.y, Ahi[ks][2], Alo[ks][2]);
            split2(a11.x, a11.y, Ahi[ks][3], Alo[ks][3]);
        }
    }

    int pbase = blockIdx.x * 16;

    // prologue: stage p0, p1; prefetch idx for p2
    {
        int a0 = idx[(pbase+0)*KK + g], a1 = idx[(pbase+0)*KK + 8 + g];
        int b0 = idx[(pbase+1)*KK + g], b1 = idx[(pbase+1)*KK + 8 + g];
        stage_point(sb + 0*ST_BYTES, pbase+0, a0, a1, w, g, qoff, lane);
        stage_point(sb + 1*ST_BYTES, pbase+1, b0, b1, w, g, qoff, lane);
    }
    int j0n = idx[(pbase+2)*KK + g], j1n = idx[(pbase+2)*KK + 8 + g];
    __syncthreads();   // sm_s/sm_q init visible; prologue stages ordered

    float sums[2], sumq[2];
    sums[0]=0.f; sums[1]=0.f; sumq[0]=0.f; sumq[1]=0.f;

    #pragma unroll 1
    for (int pi = 0; pi < 16; pi++) {
        int p = pbase + pi;
        if (pi + 2 < 16)
            stage_point(sb + ((pi+2)&3)*ST_BYTES, p + 2, j0n, j1n, w, g, qoff, lane);
        else
            CP_COMMIT();
        int pn3 = (pi + 3 < 16) ? p + 3 : pbase + 15;
        int j0f = idx[pn3*KK + g], j1f = idx[pn3*KK + 8 + g];

        CP_WAIT2();        // group pi complete
        __syncthreads();   // all warps' stages for pi visible

        uint32_t buf = sb + (pi & 3)*ST_BYTES;
        // convert own k-step (ks = w) with inline BN1 fold, publish to smem
        {
            float4 nf = lds128(buf + w*64 + qoff);
            float4 x0 = lds128(buf + 256 + (w*2+0)*512 + lane*16);
            float4 x1 = lds128(buf + 256 + (w*2+1)*512 + lane*16);
            float h00 = fmaxf(fmaf(a1v[0], x0.x - nf.x, c1v[0]), 0.f);
            float h01 = fmaxf(fmaf(a1v[1], x0.y - nf.y, c1v[1]), 0.f);
            float h02 = fmaxf(fmaf(a1v[2], x0.z - nf.z, c1v[2]), 0.f);
            float h03 = fmaxf(fmaf(a1v[3], x0.w - nf.w, c1v[3]), 0.f);
            float h10 = fmaxf(fmaf(a1v[0], x1.x - nf.x, c1v[0]), 0.f);
            float h11 = fmaxf(fmaf(a1v[1], x1.y - nf.y, c1v[1]), 0.f);
            float h12 = fmaxf(fmaf(a1v[2], x1.z - nf.z, c1v[2]), 0.f);
            float h13 = fmaxf(fmaf(a1v[3], x1.w - nf.w, c1v[3]), 0.f);
            uint32_t bh00, bl00, bh01, bl01;
            uint32_t bh10, bl10, bh11, bl11;
            split2(h00, h01, bh00, bl00);
            split2(h02, h03, bh01, bl01);
            split2(h10, h11, bh10, bl10);
            split2(h12, h13, bh11, bl11);
            sts128u(sb + CONVA_OFF + w*512 + lane*16, make_uint4(bh00, bh01, bl00, bl01));
            sts128u(sb + CONVB_OFF + w*512 + lane*16, make_uint4(bh10, bh11, bl10, bl11));
        }
        __syncthreads();   // fragments visible to all warps

        float D[2][4];
        #pragma unroll
        for (int nt = 0; nt < 2; nt++)
            #pragma unroll
            for (int i = 0; i < 4; i++) D[nt][i] = 0.f;

        #pragma unroll
        for (int ks = 0; ks < 4; ks++) {
            uint4 fa = lds128u(sb + CONVA_OFF + ks*512 + lane*16);
            uint4 fb = lds128u(sb + CONVB_OFF + ks*512 + lane*16);
            mma16816(D[0], Ahi[ks], fa.x, fa.y);
            mma16816(D[0], Alo[ks], fa.x, fa.y);
            mma16816(D[0], Ahi[ks], fa.z, fa.w);
            mma16816(D[1], Ahi[ks], fb.x, fb.y);
            mma16816(D[1], Alo[ks], fb.x, fb.y);
            mma16816(D[1], Ahi[ks], fb.z, fb.w);
        }

        // reduce over neighbors: in-thread, then shfl over q
        {
            float d00 = D[0][0], d01 = D[0][1];
            float d10 = D[1][0], d11 = D[1][1];
            float e00 = D[0][2], e01 = D[0][3];
            float e10 = D[1][2], e11 = D[1][3];
            sums[0] += (d00 + d01) + (d10 + d11);
            sums[1] += (e00 + e01) + (e10 + e11);
            sumq[0] = fmaf(d00,d00, fmaf(d01,d01, fmaf(d10,d10, fmaf(d11,d11, sumq[0]))));
            sumq[1] = fmaf(e00,e00, fmaf(e01,e01, fmaf(e10,e10, fmaf(e11,e11, sumq[1]))));
            float mx0 = fmaxf(fmaxf(d00, d01), fmaxf(d10, d11));
            float mn0 = fminf(fminf(d00, d01), fminf(d10, d11));
            float mx1 = fmaxf(fmaxf(e00, e01), fmaxf(e10, e11));
            float mn1 = fminf(fminf(e00, e01), fminf(e10, e11));
            #pragma unroll
            for (int off = 1; off < 4; off <<= 1) {
                mx0 = fmaxf(mx0, __shfl_xor_sync(0xffffffffu, mx0, off));
                mn0 = fminf(mn0, __shfl_xor_sync(0xffffffffu, mn0, off));
                mx1 = fmaxf(mx1, __shfl_xor_sync(0xffffffffu, mx1, off));
                mn1 = fminf(mn1, __shfl_xor_sync(0xffffffffu, mn1, off));
            }
            if (q == 0) {
                int ch = w*16 + g;
                g_zmax[(size_t)p*EE + ch]     = mx0;
                g_zmax[(size_t)p*EE + ch + 8] = mx1;
                g_zmin[(size_t)p*EE + ch]     = mn0;
                g_zmin[(size_t)p*EE + ch + 8] = mn1;
            }
        }
        j0n = j0f; j1n = j1f;
    }

    // BN2 sums: shfl-reduce over q, stage in smem, one global atomic per channel
    #pragma unroll
    for (int i = 0; i < 2; i++) {
        float s = sums[i], qq = sumq[i];
        #pragma unroll
        for (int off = 1; off < 4; off <<= 1) {
            s  += __shfl_xor_sync(0xffffffffu, s, off);
            qq += __shfl_xor_sync(0xffffffffu, qq, off);
        }
        if (q == 0) {
            int ch = w*16 + g + i*8;
            atomicAdd(&sm_s[ch], s);
            atomicAdd(&sm_q[ch], qq);
        }
    }
    __syncthreads();
    if (t < 64) {
        atomicAdd(&g_sum2[t],   sm_s[t]);
        atomicAdd(&g_sumsq2[t], sm_q[t]);
    }
}

// ============================================================================
// pool3 via mma.sync: out[64ch, 64pts] = W3 @ m, m = relu(a2*z_sel+c2).
// A = W3 fragments (resident), B = m^T published as pre-split bf16x2 planes.
// D fragments are the out values; BN3 partials from registers -> buckets.
__global__ void __launch_bounds__(128) k_pool3(const float* __restrict__ W3,
                                               const float* __restrict__ g2,
                                               const float* __restrict__ be2,
                                               float* __restrict__ out) {
    __shared__ uint32_t Uhi[32*65];      // [c2][pt] bf16x2 hi plane (pad 65)
    __shared__ uint32_t Ulo[32*65];      // lo plane
    __shared__ float a2s[64], c2s[64];
    int b = blockIdx.y;
    int n0 = blockIdx.x * 64;
    int t = threadIdx.x;
    int lane = t & 31, w = t >> 5;
    int g = lane >> 2, q = lane & 3;

    if (t < 64) {
        float m2 = g_sum2[t] * (1.f/CNT1);
        float v2 = fmaxf(g_sumsq2[t] * (1.f/CNT1) - m2*m2, 0.f);
        float a2o = g2[t] * rsqrtf(v2 + EPSV);
        a2s[t] = a2o;
        c2s[t] = be2[t] - a2o * m2;
    }

    // A = W3 fragments for this warp's m-tile (16 output channels)
    uint32_t Ahi[4][4], Alo[4][4];
    {
        int o0 = w*16 + g;
        #pragma unroll
        for (int ks = 0; ks < 4; ks++) {
            int cb = ks*16 + q*2;
            const float* r0 = W3 + o0*64 + cb;
            const float* r1 = W3 + (o0+8)*64 + cb;
            float2 a00 = *(const float2*)(r0);
            float2 a01 = *(const float2*)(r0 + 8);
            float2 a10 = *(const float2*)(r1);
            float2 a11 = *(const float2*)(r1 + 8);
            split2(a00.x, a00.y, Ahi[ks][0], Alo[ks][0]);
            split2(a10.x, a10.y, Ahi[ks][1], Alo[ks][1]);
            split2(a01.x, a01.y, Ahi[ks][2], Alo[ks][2]);
            split2(a11.x, a11.y, Ahi[ks][3], Alo[ks][3]);
        }
    }
    __syncthreads();    // a2s/c2s ready

    // build B planes: m^T as split bf16x2 pairs along channel dim
    {
        const float4* zmx4 = (const float4*)(g_zmax + (size_t)(b*NN + n0)*EE);
        const float4* zmn4 = (const float4*)(g_zmin + (size_t)(b*NN + n0)*EE);
        #pragma unroll
        for (int i4 = t; i4 < 1024; i4 += 128) {
            int pt = i4 >> 4;
            int c4 = i4 & 15;
            int c0 = c4 * 4;
            float4 zx = zmx4[i4];
            float4 zn = zmn4[i4];
            float a0 = a2s[c0],   cc0 = c2s[c0];
            float a1 = a2s[c0+1], cc1 = c2s[c0+1];
            float a2 = a2s[c0+2], cc2 = c2s[c0+2];
            float a3 = a2s[c0+3], cc3 = c2s[c0+3];
            float m0 = fmaxf(fmaf(a0, (a0 >= 0.f) ? zx.x : zn.x, cc0), 0.f);
            float m1 = fmaxf(fmaf(a1, (a1 >= 0.f) ? zx.y : zn.y, cc1), 0.f);
            float m2 = fmaxf(fmaf(a2, (a2 >= 0.f) ? zx.z : zn.z, cc2), 0.f);
            float m3 = fmaxf(fmaf(a3, (a3 >= 0.f) ? zx.w : zn.w, cc3), 0.f);
            uint32_t h0, l0, h1, l1;
            split2(m0, m1, h0, l0);
            split2(m2, m3, h1, l1);
            int c2a = c4 * 2;
            Uhi[c2a*65 + pt]     = h0;
            Uhi[(c2a+1)*65 + pt] = h1;
            Ulo[c2a*65 + pt]     = l0;
            Ulo[(c2a+1)*65 + pt] = l1;
        }
    }
    __syncthreads();

    int bucket = (blockIdx.y * 64 + blockIdx.x) & 31;
    float sums[2], sumq[2];
    sums[0]=0.f; sums[1]=0.f; sumq[0]=0.f; sumq[1]=0.f;

    #pragma unroll
    for (int nt = 0; nt < 8; nt++) {
        float D[4] = {0.f, 0.f, 0.f, 0.f};
        int pt = nt*8 + g;
        #pragma unroll
        for (int ks = 0; ks < 4; ks++) {
            uint32_t bh0 = Uhi[(ks*8 + q)*65 + pt];
            uint32_t bh1 = Uhi[(ks*8 + q + 4)*65 + pt];
            uint32_t bl0 = Ulo[(ks*8 + q)*65 + pt];
            uint32_t bl1 = Ulo[(ks*8 + q + 4)*65 + pt];
            mma16816(D, Ahi[ks], bh0, bh1);
            mma16816(D, Alo[ks], bh0, bh1);
            mma16816(D, Ahi[ks], bl0, bl1);
        }
        int ch = w*16 + g;
        int pcol = n0 + nt*8 + q*2;
        *(float2*)(out + (size_t)(b*EE + ch)*NN + pcol)     = make_float2(D[0], D[1]);
        *(float2*)(out + (size_t)(b*EE + ch + 8)*NN + pcol) = make_float2(D[2], D[3]);
        sums[0] += D[0] + D[1];
        sums[1] += D[2] + D[3];
        sumq[0] = fmaf(D[0],D[0], fmaf(D[1],D[1], sumq[0]));
        sumq[1] = fmaf(D[2],D[2], fmaf(D[3],D[3], sumq[1]));
    }

    // BN3 partials: shfl over q (points), then bucket atomics per channel
    #pragma unroll
    for (int i = 0; i < 2; i++) {
        float s = sums[i], qv = sumq[i];
        #pragma unroll
        for (int off = 1; off < 4; off <<= 1) {
            s  += __shfl_xor_sync(0xffffffffu, s, off);
            qv += __shfl_xor_sync(0xffffffffu, qv, off);
        }
        if (q == 0) {
            int ch = w*16 + g + i*8;
            atomicAdd(&g_bs3[bucket][ch], s);
            atomicAdd(&g_bs3[bucket][64 + ch], qv);
        }
    }
}

// BN3 + ReLU in place (folds the 32 buckets first)
__global__ void k_out(const float* __restrict__ g3, const float* __restrict__ be3,
                      float* __restrict__ out) {
    __shared__ float sa[EE], sc[EE];
    int t = threadIdx.x;
    if (t < EE) {
        float s = 0.f, qv = 0.f;
        #pragma unroll
        for (int bk = 0; bk < 32; bk++) {
            s  += g_bs3[bk][t];
            qv += g_bs3[bk][64 + t];
        }
        float m3 = s * (1.f/CNT3);
        float v3 = fmaxf(qv * (1.f/CNT3) - m3*m3, 0.f);
        float a3 = g3[t] * rsqrtf(v3 + EPSV);
        sa[t] = a3;
        sc[t] = be3[t] - a3 * m3;
    }
    __syncthreads();
    int gi = blockIdx.x * blockDim.x + t;
    int o = (gi >> 10) & 63;
    float4* out4 = (float4*)out;
    float4 v = out4[gi];
    float a = sa[o], c = sc[o];
    v.x = fmaxf(fmaf(a, v.x, c), 0.f);
    v.y = fmaxf(fmaf(a, v.y, c), 0.f);
    v.z = fmaxf(fmaf(a, v.z, c), 0.f);
    v.w = fmaxf(fmaf(a, v.w, c), 0.f);
    out4[gi] = v;
}

extern "C" void kernel_launch(void* const* d_in, const int* in_sizes, int n_in,
                              void* d_out, int out_size) {
    const float* x   = (const float*)d_in[0];
    const int*   idx = (const int*)  d_in[1];
    const float* W1  = (const float*)d_in[2];
    const float* g1  = (const float*)d_in[4];
    const float* be1 = (const float*)d_in[5];
    const float* W2  = (const float*)d_in[6];
    const float* g2  = (const float*)d_in[8];
    const float* be2 = (const float*)d_in[9];
    const float* W3  = (const float*)d_in[10];
    const float* g3  = (const float*)d_in[12];
    const float* be3 = (const float*)d_in[13];
    float* out = (float*)d_out;

    cudaFuncSetAttribute(k_edge, cudaFuncAttributeMaxDynamicSharedMemorySize, EDGE_SMEM);

    k_y1    <<<dim3(64, 8), 256>>>(x, W1);
    k_stats1<<<512, 256>>>(idx);
    k_edge  <<<2048, 128, EDGE_SMEM>>>(idx, W2, g1, be1);
    k_pool3 <<<dim3(64, 8), 128>>>(W3, g2, be2, out);
    k_out   <<<2048, 256>>>(g3, be3, out);
}

// round 16
// speedup vs baseline: 1.4189x; 1.1094x over previous
#include <cuda_runtime.h>
#include <cuda_bf16.h>
#include <cstdint>

#define BB 8
#define CC 64
#define NN 4096
#define KK 16
#define EE 64
#define NPOINTS (BB*NN)            // 32768
#define CNT1 524288.0f             // B*N*K
#define CNT3 32768.0f              // B*N
#define EPSV 1e-5f

// ---- scratch (device globals: allocation-free rule) ----
// g_y1t holds y1 in PERMUTED channel layout: phys float4 slot (blk, q) holds
// orig channels {blk*16+2q, +1, blk*16+2q+8, +9}
__device__ float g_y1t[NPOINTS*EE];       // 8 MB
__device__ float g_zmax[NPOINTS*EE];      // 8 MB
__device__ float g_zmin[NPOINTS*EE];      // 8 MB
__device__ float g_sum1[EE], g_sumsq1[EE];   // PHYS channel order
__device__ float g_sum2[EE], g_sumsq2[EE];
__device__ float g_bs3[32][128];          // BN3 bucketed partials

// pack two fp32 into bf16x2 (first arg -> low half)
__device__ __forceinline__ uint32_t pack_bf2(float lo_e, float hi_e) {
    uint32_t r;
    asm("cvt.rn.bf16x2.f32 %0, %1, %2;" : "=r"(r) : "f"(hi_e), "f"(lo_e));
    return r;
}

__device__ __forceinline__ void mma16816(float d[4], const uint32_t a[4], uint32_t b0, uint32_t b1) {
    asm volatile(
        "mma.sync.aligned.m16n8k16.row.col.f32.bf16.bf16.f32 "
        "{%0,%1,%2,%3}, {%4,%5,%6,%7}, {%8,%9}, {%0,%1,%2,%3};"
        : "+f"(d[0]), "+f"(d[1]), "+f"(d[2]), "+f"(d[3])
        : "r"(a[0]), "r"(a[1]), "r"(a[2]), "r"(a[3]), "r"(b0), "r"(b1));
}

// split a packed pair (x,y) into hi (bf16) and lo (residual bf16)
__device__ __forceinline__ void split2(float x, float y, uint32_t& hi, uint32_t& lo) {
    hi = pack_bf2(x, y);
    float e0 = __uint_as_float(hi << 16);
    float e1 = __uint_as_float(hi & 0xffff0000u);
    lo = pack_bf2(x - e0, y - e1);
}

__device__ __forceinline__ uint32_t smem_u32(const void* p) {
    uint32_t a;
    asm("{ .reg .u64 t; cvta.to.shared.u64 t, %1; cvt.u32.u64 %0, t; }" : "=r"(a) : "l"(p));
    return a;
}
__device__ __forceinline__ float4 lds128(uint32_t a) {
    float4 v;
    asm volatile("ld.shared.v4.f32 {%0,%1,%2,%3}, [%4];"
                 : "=f"(v.x), "=f"(v.y), "=f"(v.z), "=f"(v.w) : "r"(a));
    return v;
}
__device__ __forceinline__ uint4 lds128u(uint32_t a) {
    uint4 v;
    asm volatile("ld.shared.v4.u32 {%0,%1,%2,%3}, [%4];"
                 : "=r"(v.x), "=r"(v.y), "=r"(v.z), "=r"(v.w) : "r"(a));
    return v;
}
__device__ __forceinline__ void sts128u(uint32_t a, uint4 v) {
    asm volatile("st.shared.v4.u32 [%0], {%1,%2,%3,%4};"
                 :: "r"(a), "r"(v.x), "r"(v.y), "r"(v.z), "r"(v.w) : "memory");
}
#define CP16(d, s) asm volatile("cp.async.cg.shared.global [%0], [%1], 16;" :: "r"(d), "l"(s) : "memory")
#define CP_COMMIT() asm volatile("cp.async.commit_group;" ::: "memory")
#define CP_WAIT2()  asm volatile("cp.async.wait_group 2;" ::: "memory")

// ============================================================================
// k_y1 via mma.sync: y1[64e, 64pts] = W1 @ x_tile, stored PERMUTED point-major.
// A = W1 fragments (resident), B = x planes (split bf16x2 along channel pairs).
__global__ void __launch_bounds__(128) k_y1(const float* __restrict__ x,
                                            const float* __restrict__ W1) {
    __shared__ uint32_t Uhi[32*65];
    __shared__ uint32_t Ulo[32*65];
    __shared__ float sD[64*65];
    int b = blockIdx.y;
    int n0 = blockIdx.x * 64;
    int t = threadIdx.x;
    int lane = t & 31, w = t >> 5;
    int g = lane >> 2, q = lane & 3;

    if (blockIdx.x == 0 && blockIdx.y == 0) {
        if (t < EE) {
            g_sum1[t]=0.f; g_sumsq1[t]=0.f;
            g_sum2[t]=0.f; g_sumsq2[t]=0.f;
        }
        for (int i = t; i < 32*128; i += 128) ((float*)g_bs3)[i] = 0.f;
    }

    // A = W1 fragments for this warp's m-tile (16 output channels)
    uint32_t Ahi[4][4], Alo[4][4];
    {
        int o0 = w*16 + g;
        #pragma unroll
        for (int ks = 0; ks < 4; ks++) {
            int cb = ks*16 + q*2;
            const float* r0 = W1 + o0*64 + cb;
            const float* r1 = W1 + (o0+8)*64 + cb;
            float2 a00 = *(const float2*)(r0);
            float2 a01 = *(const float2*)(r0 + 8);
            float2 a10 = *(const float2*)(r1);
            float2 a11 = *(const float2*)(r1 + 8);
            split2(a00.x, a00.y, Ahi[ks][0], Alo[ks][0]);
            split2(a10.x, a10.y, Ahi[ks][1], Alo[ks][1]);
            split2(a01.x, a01.y, Ahi[ks][2], Alo[ks][2]);
            split2(a11.x, a11.y, Ahi[ks][3], Alo[ks][3]);
        }
    }

    // B planes from x: Uhi/Ulo[c2][pt] = split bf16x2 of (x[2c2][pt], x[2c2+1][pt])
    #pragma unroll
    for (int i4 = t; i4 < 2048; i4 += 128) {
        int c2 = i4 >> 6;
        int pt = i4 & 63;
        float xa = x[(size_t)(b*CC + 2*c2)*NN + n0 + pt];
        float xb = x[(size_t)(b*CC + 2*c2 + 1)*NN + n0 + pt];
        uint32_t h, l;
        split2(xa, xb, h, l);
        Uhi[c2*65 + pt] = h;
        Ulo[c2*65 + pt] = l;
    }
    __syncthreads();

    // MMA: D[e][pt], staged to sD
    #pragma unroll
    for (int nt = 0; nt < 8; nt++) {
        float D[4] = {0.f, 0.f, 0.f, 0.f};
        int pt = nt*8 + g;
        #pragma unroll
        for (int ks = 0; ks < 4; ks++) {
            uint32_t bh0 = Uhi[(ks*8 + q)*65 + pt];
            uint32_t bh1 = Uhi[(ks*8 + q + 4)*65 + pt];
            uint32_t bl0 = Ulo[(ks*8 + q)*65 + pt];
            uint32_t bl1 = Ulo[(ks*8 + q + 4)*65 + pt];
            mma16816(D, Ahi[ks], bh0, bh1);
            mma16816(D, Alo[ks], bh0, bh1);
            mma16816(D, Ahi[ks], bl0, bl1);
        }
        int ch = w*16 + g;
        int pc = nt*8 + q*2;
        sD[ch*65 + pc]     = D[0];
        sD[ch*65 + pc + 1] = D[1];
        sD[(ch+8)*65 + pc]     = D[2];
        sD[(ch+8)*65 + pc + 1] = D[3];
    }
    __syncthreads();

    // permuted coalesced store: phys slot (blk, qp) <- orig {blk*16+2qp,+1,+2qp+8,+9}
    #pragma unroll
    for (int i = t; i < 1024; i += 128) {
        int pt = i >> 4;
        int s4 = i & 15;
        int blk = s4 >> 2, qp = s4 & 3;
        int ob = blk*16 + qp*2;
        float4 v;
        v.x = sD[ob*65 + pt];
        v.y = sD[(ob+1)*65 + pt];
        v.z = sD[(ob+8)*65 + pt];
        v.w = sD[(ob+9)*65 + pt];
        *(float4*)(g_y1t + (size_t)(b*NN + n0 + pt)*EE + s4*4) = v;
    }
}

// BN1 stats over d = y_j - y_n (permuted data -> sums in PHYS order)
__global__ void k_stats1(const int* __restrict__ idx) {
    __shared__ float4 red_s[16][16];
    __shared__ float4 red_q[16][16];
    int t = threadIdx.x;
    int c4 = t & 15, g = t >> 4;
    float4 s = make_float4(0.f,0.f,0.f,0.f);
    float4 q = make_float4(0.f,0.f,0.f,0.f);
    int p0 = blockIdx.x * 64;
    #pragma unroll 1
    for (int pl = 0; pl < 4; pl++) {
        int point = p0 + g*4 + pl;
        int brow = point & ~(NN-1);
        int jown = idx[point*KK + c4];
        float4 yn = *(const float4*)(g_y1t + (size_t)point*EE + c4*4);
        #pragma unroll
        for (int k = 0; k < KK; k++) {
            int j = __shfl_sync(0xffffffffu, jown, ((t & 31) & 16) | k, 32);
            float4 yj = *(const float4*)(g_y1t + (size_t)(brow + j)*EE + c4*4);
            float dx = yj.x - yn.x, dy = yj.y - yn.y, dz = yj.z - yn.z, dw = yj.w - yn.w;
            s.x += dx; s.y += dy; s.z += dz; s.w += dw;
            q.x = fmaf(dx, dx, q.x); q.y = fmaf(dy, dy, q.y);
            q.z = fmaf(dz, dz, q.z); q.w = fmaf(dw, dw, q.w);
        }
    }
    red_s[g][c4] = s;
    red_q[g][c4] = q;
    __syncthreads();
    if (t < 64) {
        float ss = 0.f, qq = 0.f;
        #pragma unroll
        for (int gg = 0; gg < 16; gg++) {
            ss += ((const float*)&red_s[gg][t >> 2])[t & 3];
            qq += ((const float*)&red_q[gg][t >> 2])[t & 3];
        }
        atomicAdd(&g_sum1[t], ss);
        atomicAdd(&g_sumsq1[t], qq);
    }
}

// ============================================================================
// Main pass: 4 warps share one point stream (16 pts/CTA); warp w owns m-tile w
// and converts only k-step w (shared via smem). 4-stage cp.async ring.
// BN1 fold applied inline in the convert (a1/c1 register-resident).
#define ST_BYTES  4352                   // 256 cen + 8*512 neighbor chunks
#define CONVA_OFF (4*ST_BYTES)           // 17408
#define CONVB_OFF (CONVA_OFF + 2048)     // 19456
#define RED_OFF   (CONVA_OFF + 4096)     // 21504
#define EDGE_SMEM (RED_OFF + 512)        // 22016

__device__ __forceinline__ void stage_point(uint32_t sbuf, int p, int j0, int j1,
                                            int w, int g, int qoff, int lane) {
    int base = p & ~(NN-1);
    const char* cen = (const char*)g_y1t + (((size_t)p) << 8);
    const char* r0  = (const char*)g_y1t + (((size_t)(base + j0)) << 8);
    const char* r1  = (const char*)g_y1t + (((size_t)(base + j1)) << 8);
    int ko = w*64 + qoff;
    if (g == 0) CP16(sbuf + ko, cen + ko);                    // cen stored once
    CP16(sbuf + 256 + (w*2+0)*512 + lane*16, r0 + ko);
    CP16(sbuf + 256 + (w*2+1)*512 + lane*16, r1 + ko);
    CP_COMMIT();
}

__global__ void __launch_bounds__(128, 6) k_edge(const int* __restrict__ idx,
                                                 const float* __restrict__ W2,
                                                 const float* __restrict__ g1,
                                                 const float* __restrict__ be1) {
    extern __shared__ char esm[];
    uint32_t sb = smem_u32(esm);
    float* sm_s = (float*)(esm + RED_OFF);
    float* sm_q = sm_s + 64;
    int t = threadIdx.x;
    int lane = t & 31, w = t >> 5;
    int g = lane >> 2, q = lane & 3;
    int qoff = q * 16;

    if (t < 64) { sm_s[t] = 0.f; sm_q[t] = 0.f; }

    // BN1 fold for this thread's 4 phys channels (k-step w, float slice q*4)
    float a1v[4], c1v[4];
    #pragma unroll
    for (int j = 0; j < 4; j++) {
        int phys = w*16 + q*4 + j;
        int orig = w*16 + ((j < 2) ? (q*2 + j) : (q*2 + 8 + (j - 2)));
        float m1 = g_sum1[phys] * (1.f/CNT1);
        float v1 = fmaxf(g_sumsq1[phys] * (1.f/CNT1) - m1*m1, 0.f);
        a1v[j] = g1[orig] * rsqrtf(v1 + EPSV);
        c1v[j] = be1[orig] - a1v[j] * m1;
    }

    // A = W2 fragments for this warp's single m-tile (16 output channels)
    uint32_t Ahi[4][4], Alo[4][4];
    {
        int o0 = w*16 + g;
        #pragma unroll
        for (int ks = 0; ks < 4; ks++) {
            int cb = ks*16 + q*2;
            const float* r0 = W2 + o0*64 + cb;
            const float* r1 = W2 + (o0+8)*64 + cb;
            float2 a00 = *(const float2*)(r0);
            float2 a01 = *(const float2*)(r0 + 8);
            float2 a10 = *(const float2*)(r1);
            float2 a11 = *(const float2*)(r1 + 8);
            split2(a00.x, a00.y, Ahi[ks][0], Alo[ks][0]);
            split2(a10.x, a10.y, Ahi[ks][1], Alo[ks][1]);
            split2(a01.x, a01.y, Ahi[ks][2], Alo[ks][2]);
            split2(a11.x, a11.y, Ahi[ks][3], Alo[ks][3]);
        }
    }

    int pbase = blockIdx.x * 16;

    // prologue: stage p0, p1; prefetch idx for p2
    {
        int a0 = idx[(pbase+0)*KK + g], a1 = idx[(pbase+0)*KK + 8 + g];
        int b0 = idx[(pbase+1)*KK + g], b1 = idx[(pbase+1)*KK + 8 + g];
        stage_point(sb + 0*ST_BYTES, pbase+0, a0, a1, w, g, qoff, lane);
        stage_point(sb + 1*ST_BYTES, pbase+1, b0, b1, w, g, qoff, lane);
    }
    int j0n = idx[(pbase+2)*KK + g], j1n = idx[(pbase+2)*KK + 8 + g];
    __syncthreads();   // sm_s/sm_q init visible; prologue stages ordered

    float sums[2], sumq[2];
    sums[0]=0.f; sums[1]=0.f; sumq[0]=0.f; sumq[1]=0.f;

    #pragma unroll 1
    for (int pi = 0; pi < 16; pi++) {
        int p = pbase + pi;
        if (pi + 2 < 16)
            stage_point(sb + ((pi+2)&3)*ST_BYTES, p + 2, j0n, j1n, w, g, qoff, lane);
        else
            CP_COMMIT();
        int pn3 = (pi + 3 < 16) ? p + 3 : pbase + 15;
        int j0f = idx[pn3*KK + g], j1f = idx[pn3*KK + 8 + g];

        CP_WAIT2();        // group pi complete
        __syncthreads();   // all warps' stages for pi visible

        uint32_t buf = sb + (pi & 3)*ST_BYTES;
        // convert own k-step (ks = w) with inline BN1 fold, publish to smem
        {
            float4 nf = lds128(buf + w*64 + qoff);
            float4 x0 = lds128(buf + 256 + (w*2+0)*512 + lane*16);
            float4 x1 = lds128(buf + 256 + (w*2+1)*512 + lane*16);
            float h00 = fmaxf(fmaf(a1v[0], x0.x - nf.x, c1v[0]), 0.f);
            float h01 = fmaxf(fmaf(a1v[1], x0.y - nf.y, c1v[1]), 0.f);
            float h02 = fmaxf(fmaf(a1v[2], x0.z - nf.z, c1v[2]), 0.f);
            float h03 = fmaxf(fmaf(a1v[3], x0.w - nf.w, c1v[3]), 0.f);
            float h10 = fmaxf(fmaf(a1v[0], x1.x - nf.x, c1v[0]), 0.f);
            float h11 = fmaxf(fmaf(a1v[1], x1.y - nf.y, c1v[1]), 0.f);
            float h12 = fmaxf(fmaf(a1v[2], x1.z - nf.z, c1v[2]), 0.f);
            float h13 = fmaxf(fmaf(a1v[3], x1.w - nf.w, c1v[3]), 0.f);
            uint32_t bh00, bl00, bh01, bl01;
            uint32_t bh10, bl10, bh11, bl11;
            split2(h00, h01, bh00, bl00);
            split2(h02, h03, bh01, bl01);
            split2(h10, h11, bh10, bl10);
            split2(h12, h13, bh11, bl11);
            sts128u(sb + CONVA_OFF + w*512 + lane*16, make_uint4(bh00, bh01, bl00, bl01));
            sts128u(sb + CONVB_OFF + w*512 + lane*16, make_uint4(bh10, bh11, bl10, bl11));
        }
        __syncthreads();   // fragments visible to all warps

        float D[2][4];
        #pragma unroll
        for (int nt = 0; nt < 2; nt++)
            #pragma unroll
            for (int i = 0; i < 4; i++) D[nt][i] = 0.f;

        #pragma unroll
        for (int ks = 0; ks < 4; ks++) {
            uint4 fa = lds128u(sb + CONVA_OFF + ks*512 + lane*16);
            uint4 fb = lds128u(sb + CONVB_OFF + ks*512 + lane*16);
            mma16816(D[0], Ahi[ks], fa.x, fa.y);
            mma16816(D[0], Alo[ks], fa.x, fa.y);
            mma16816(D[0], Ahi[ks], fa.z, fa.w);
            mma16816(D[1], Ahi[ks], fb.x, fb.y);
            mma16816(D[1], Alo[ks], fb.x, fb.y);
            mma16816(D[1], Ahi[ks], fb.z, fb.w);
        }

        // reduce over neighbors: in-thread, then shfl over q
        {
            float d00 = D[0][0], d01 = D[0][1];
            float d10 = D[1][0], d11 = D[1][1];
            float e00 = D[0][2], e01 = D[0][3];
            float e10 = D[1][2], e11 = D[1][3];
            sums[0] += (d00 + d01) + (d10 + d11);
            sums[1] += (e00 + e01) + (e10 + e11);
            sumq[0] = fmaf(d00,d00, fmaf(d01,d01, fmaf(d10,d10, fmaf(d11,d11, sumq[0]))));
            sumq[1] = fmaf(e00,e00, fmaf(e01,e01, fmaf(e10,e10, fmaf(e11,e11, sumq[1]))));
            float mx0 = fmaxf(fmaxf(d00, d01), fmaxf(d10, d11));
            float mn0 = fminf(fminf(d00, d01), fminf(d10, d11));
            float mx1 = fmaxf(fmaxf(e00, e01), fmaxf(e10, e11));
            float mn1 = fminf(fminf(e00, e01), fminf(e10, e11));
            #pragma unroll
            for (int off = 1; off < 4; off <<= 1) {
                mx0 = fmaxf(mx0, __shfl_xor_sync(0xffffffffu, mx0, off));
                mn0 = fminf(mn0, __shfl_xor_sync(0xffffffffu, mn0, off));
                mx1 = fmaxf(mx1, __shfl_xor_sync(0xffffffffu, mx1, off));
                mn1 = fminf(mn1, __shfl_xor_sync(0xffffffffu, mn1, off));
            }
            if (q == 0) {
                int ch = w*16 + g;
                g_zmax[(size_t)p*EE + ch]     = mx0;
                g_zmax[(size_t)p*EE + ch + 8] = mx1;
                g_zmin[(size_t)p*EE + ch]     = mn0;
                g_zmin[(size_t)p*EE + ch + 8] = mn1;
            }
        }
        j0n = j0f; j1n = j1f;
    }

    // BN2 sums: shfl-reduce over q, stage in smem, one global atomic per channel
    #pragma unroll
    for (int i = 0; i < 2; i++) {
        float s = sums[i], qq = sumq[i];
        #pragma unroll
        for (int off = 1; off < 4; off <<= 1) {
            s  += __shfl_xor_sync(0xffffffffu, s, off);
            qq += __shfl_xor_sync(0xffffffffu, qq, off);
        }
        if (q == 0) {
            int ch = w*16 + g + i*8;
            atomicAdd(&sm_s[ch], s);
            atomicAdd(&sm_q[ch], qq);
        }
    }
    __syncthreads();
    if (t < 64) {
        atomicAdd(&g_sum2[t],   sm_s[t]);
        atomicAdd(&g_sumsq2[t], sm_q[t]);
    }
}

// ============================================================================
// pool3 via mma.sync: out[64ch, 64pts] = W3 @ m, m = relu(a2*z_sel+c2).
__global__ void __launch_bounds__(128) k_pool3(const float* __restrict__ W3,
                                               const float* __restrict__ g2,
                                               const float* __restrict__ be2,
                                               float* __restrict__ out) {
    __shared__ uint32_t Uhi[32*65];
    __shared__ uint32_t Ulo[32*65];
    __shared__ float a2s[64], c2s[64];
    int b = blockIdx.y;
    int n0 = blockIdx.x * 64;
    int t = threadIdx.x;
    int lane = t & 31, w = t >> 5;
    int g = lane >> 2, q = lane & 3;

    if (t < 64) {
        float m2 = g_sum2[t] * (1.f/CNT1);
        float v2 = fmaxf(g_sumsq2[t] * (1.f/CNT1) - m2*m2, 0.f);
        float a2o = g2[t] * rsqrtf(v2 + EPSV);
        a2s[t] = a2o;
        c2s[t] = be2[t] - a2o * m2;
    }

    // A = W3 fragments for this warp's m-tile (16 output channels)
    uint32_t Ahi[4][4], Alo[4][4];
    {
        int o0 = w*16 + g;
        #pragma unroll
        for (int ks = 0; ks < 4; ks++) {
            int cb = ks*16 + q*2;
            const float* r0 = W3 + o0*64 + cb;
            const float* r1 = W3 + (o0+8)*64 + cb;
            float2 a00 = *(const float2*)(r0);
            float2 a01 = *(const float2*)(r0 + 8);
            float2 a10 = *(const float2*)(r1);
            float2 a11 = *(const float2*)(r1 + 8);
            split2(a00.x, a00.y, Ahi[ks][0], Alo[ks][0]);
            split2(a10.x, a10.y, Ahi[ks][1], Alo[ks][1]);
            split2(a01.x, a01.y, Ahi[ks][2], Alo[ks][2]);
            split2(a11.x, a11.y, Ahi[ks][3], Alo[ks][3]);
        }
    }
    __syncthreads();    // a2s/c2s ready

    // build B planes: m^T as split bf16x2 pairs along channel dim
    {
        const float4* zmx4 = (const float4*)(g_zmax + (size_t)(b*NN + n0)*EE);
        const float4* zmn4 = (const float4*)(g_zmin + (size_t)(b*NN + n0)*EE);
        #pragma unroll
        for (int i4 = t; i4 < 1024; i4 += 128) {
            int pt = i4 >> 4;
            int c4 = i4 & 15;
            int c0 = c4 * 4;
            float4 zx = zmx4[i4];
            float4 zn = zmn4[i4];
            float a0 = a2s[c0],   cc0 = c2s[c0];
            float a1 = a2s[c0+1], cc1 = c2s[c0+1];
            float a2 = a2s[c0+2], cc2 = c2s[c0+2];
            float a3 = a2s[c0+3], cc3 = c2s[c0+3];
            float m0 = fmaxf(fmaf(a0, (a0 >= 0.f) ? zx.x : zn.x, cc0), 0.f);
            float m1 = fmaxf(fmaf(a1, (a1 >= 0.f) ? zx.y : zn.y, cc1), 0.f);
            float m2 = fmaxf(fmaf(a2, (a2 >= 0.f) ? zx.z : zn.z, cc2), 0.f);
            float m3 = fmaxf(fmaf(a3, (a3 >= 0.f) ? zx.w : zn.w, cc3), 0.f);
            uint32_t h0, l0, h1, l1;
            split2(m0, m1, h0, l0);
            split2(m2, m3, h1, l1);
            int c2a = c4 * 2;
            Uhi[c2a*65 + pt]     = h0;
            Uhi[(c2a+1)*65 + pt] = h1;
            Ulo[c2a*65 + pt]     = l0;
            Ulo[(c2a+1)*65 + pt] = l1;
        }
    }
    __syncthreads();

    int bucket = (blockIdx.y * 64 + blockIdx.x) & 31;
    float sums[2], sumq[2];
    sums[0]=0.f; sums[1]=0.f; sumq[0]=0.f; sumq[1]=0.f;

    #pragma unroll
    for (int nt = 0; nt < 8; nt++) {
        float D[4] = {0.f, 0.f, 0.f, 0.f};
        int pt = nt*8 + g;
        #pragma unroll
        for (int ks = 0; ks < 4; ks++) {
            uint32_t bh0 = Uhi[(ks*8 + q)*65 + pt];
            uint32_t bh1 = Uhi[(ks*8 + q + 4)*65 + pt];
            uint32_t bl0 = Ulo[(ks*8 + q)*65 + pt];
            uint32_t bl1 = Ulo[(ks*8 + q + 4)*65 + pt];
            mma16816(D, Ahi[ks], bh0, bh1);
            mma16816(D, Alo[ks], bh0, bh1);
            mma16816(D, Ahi[ks], bl0, bl1);
        }
        int ch = w*16 + g;
        int pcol = n0 + nt*8 + q*2;
        *(float2*)(out + (size_t)(b*EE + ch)*NN + pcol)     = make_float2(D[0], D[1]);
        *(float2*)(out + (size_t)(b*EE + ch + 8)*NN + pcol) = make_float2(D[2], D[3]);
        sums[0] += D[0] + D[1];
        sums[1] += D[2] + D[3];
        sumq[0] = fmaf(D[0],D[0], fmaf(D[1],D[1], sumq[0]));
        sumq[1] = fmaf(D[2],D[2], fmaf(D[3],D[3], sumq[1]));
    }

    // BN3 partials: shfl over q (points), then bucket atomics per channel
    #pragma unroll
    for (int i = 0; i < 2; i++) {
        float s = sums[i], qv = sumq[i];
        #pragma unroll
        for (int off = 1; off < 4; off <<= 1) {
            s  += __shfl_xor_sync(0xffffffffu, s, off);
            qv += __shfl_xor_sync(0xffffffffu, qv, off);
        }
        if (q == 0) {
            int ch = w*16 + g + i*8;
            atomicAdd(&g_bs3[bucket][ch], s);
            atomicAdd(&g_bs3[bucket][64 + ch], qv);
        }
    }
}

// BN3 + ReLU in place (folds the 32 buckets first)
__global__ void k_out(const float* __restrict__ g3, const float* __restrict__ be3,
                      float* __restrict__ out) {
    __shared__ float sa[EE], sc[EE];
    int t = threadIdx.x;
    if (t < EE) {
        float s = 0.f, qv = 0.f;
        #pragma unroll
        for (int bk = 0; bk < 32; bk++) {
            s  += g_bs3[bk][t];
            qv += g_bs3[bk][64 + t];
        }
        float m3 = s * (1.f/CNT3);
        float v3 = fmaxf(qv * (1.f/CNT3) - m3*m3, 0.f);
        float a3 = g3[t] * rsqrtf(v3 + EPSV);
        sa[t] = a3;
        sc[t] = be3[t] - a3 * m3;
    }
    __syncthreads();
    int gi = blockIdx.x * blockDim.x + t;
    int o = (gi >> 10) & 63;
    float4* out4 = (float4*)out;
    float4 v = out4[gi];
    float a = sa[o], c = sc[o];
    v.x = fmaxf(fmaf(a, v.x, c), 0.f);
    v.y = fmaxf(fmaf(a, v.y, c), 0.f);
    v.z = fmaxf(fmaf(a, v.z, c), 0.f);
    v.w = fmaxf(fmaf(a, v.w, c), 0.f);
    out4[gi] = v;
}

extern "C" void kernel_launch(void* const* d_in, const int* in_sizes, int n_in,
                              void* d_out, int out_size) {
    const float* x   = (const float*)d_in[0];
    const int*   idx = (const int*)  d_in[1];
    const float* W1  = (const float*)d_in[2];
    const float* g1  = (const float*)d_in[4];
    const float* be1 = (const float*)d_in[5];
    const float* W2  = (const float*)d_in[6];
    const float* g2  = (const float*)d_in[8];
    const float* be2 = (const float*)d_in[9];
    const float* W3  = (const float*)d_in[10];
    const float* g3  = (const float*)d_in[12];
    const float* be3 = (const float*)d_in[13];
    float* out = (float*)d_out;

    cudaFuncSetAttribute(k_edge, cudaFuncAttributeMaxDynamicSharedMemorySize, EDGE_SMEM);

    k_y1    <<<dim3(64, 8), 128>>>(x, W1);
    k_stats1<<<512, 256>>>(idx);
    k_edge  <<<2048, 128, EDGE_SMEM>>>(idx, W2, g1, be1);
    k_pool3 <<<dim3(64, 8), 128>>>(W3, g2, be2, out);
    k_out   <<<2048, 256>>>(g3, be3, out);
}